// round 2
// baseline (speedup 1.0000x reference)
#include <cuda_runtime.h>
#include <math.h>

#define B_   128
#define S_   64
#define F_   32
#define D_   128
#define U_   128
#define DS_  128
#define SFD  262144          // S*F*D
#define NTILES 2049          // DIN / 128
#define G_   296             // split-K groups for big GEMM (2 exact waves at 2 blk/SM)

// deterministic split-K scratch: [G_][2][128][128]
__device__ float g_partial[(size_t)G_ * 2 * 128 * 128];
__device__ float g_wsel[B_ * F_];

// ---------------------------------------------------------------------------
// Kernel 1: C[which] = v @ W(which), split-K over 128-wide tiles, 8x8 microtile
// v[b,k] = inputs[b*SFD + k] for k < SFD, else static[b*128 + (k-SFD)]
// ---------------------------------------------------------------------------
__global__ __launch_bounds__(256, 2) void k_biggemm(
    const float* __restrict__ inputs, const float* __restrict__ stat,
    const float* __restrict__ cWe, const float* __restrict__ cWp)
{
    const int g = blockIdx.x, which = blockIdx.y;
    const float* __restrict__ W = which ? cWp : cWe;

    __shared__ float As[8][128];
    __shared__ float Bs[8][128];

    float acc[8][8];
#pragma unroll
    for (int i = 0; i < 8; i++)
#pragma unroll
        for (int j = 0; j < 8; j++) acc[i][j] = 0.f;

    const int t  = threadIdx.x;
    const int tx = t & 15, ty = t >> 4;
    const int lm = t >> 1;          // A-load row (0..127)
    const int lc = (t & 1) * 4;     // A-load col offset within 8
    const int bk = t >> 5;          // B-load k row (0..7)
    const int bn = (t & 31) * 4;    // B-load col

    for (int tile = g; tile < NTILES; tile += G_) {
        const float* vb; long vstr;
        if (tile < 2048) { vb = inputs + (long)tile * 128; vstr = SFD; }
        else             { vb = stat;                      vstr = DS_; }
        const float* Wb = W + (long)tile * 128 * 128;

        for (int kk = 0; kk < 128; kk += 8) {
            float4 av = *(const float4*)(vb + (long)lm * vstr + kk + lc);
            float4 bv = *(const float4*)(Wb + (kk + bk) * 128 + bn);
            __syncthreads();   // protect previous compute's smem reads
            As[lc + 0][lm] = av.x; As[lc + 1][lm] = av.y;
            As[lc + 2][lm] = av.z; As[lc + 3][lm] = av.w;
            *(float4*)(&Bs[bk][bn]) = bv;
            __syncthreads();
#pragma unroll
            for (int k = 0; k < 8; k++) {
                float4 a0 = *(const float4*)(&As[k][ty * 8]);
                float4 a1 = *(const float4*)(&As[k][ty * 8 + 4]);
                float4 b0 = *(const float4*)(&Bs[k][tx * 8]);
                float4 b1 = *(const float4*)(&Bs[k][tx * 8 + 4]);
                float a[8] = {a0.x, a0.y, a0.z, a0.w, a1.x, a1.y, a1.z, a1.w};
                float b[8] = {b0.x, b0.y, b0.z, b0.w, b1.x, b1.y, b1.z, b1.w};
#pragma unroll
                for (int i = 0; i < 8; i++)
#pragma unroll
                    for (int j = 0; j < 8; j++) acc[i][j] += a[i] * b[j];
            }
        }
    }

    float* dst = g_partial + ((long)g * 2 + which) * 16384;
#pragma unroll
    for (int i = 0; i < 8; i++)
#pragma unroll
        for (int j = 0; j < 8; j += 4) {
            float4 v4 = make_float4(acc[i][j], acc[i][j+1], acc[i][j+2], acc[i][j+3]);
            *(float4*)(dst + (ty * 8 + i) * 128 + tx * 8 + j) = v4;
        }
}

// ---------------------------------------------------------------------------
// Kernel 2: selection head. One block per batch row, 128 threads.
// Reduces split-K partials, runs grn_concat + softmax dense -> g_wsel[B,F].
// ---------------------------------------------------------------------------
__global__ __launch_bounds__(128) void k_select(
    const float* __restrict__ cbe,
    const float* __restrict__ cWl,  const float* __restrict__ cbl,
    const float* __restrict__ cWgl, const float* __restrict__ cbgl,
    const float* __restrict__ cWgs, const float* __restrict__ cbgs,
    const float* __restrict__ cgamma, const float* __restrict__ cbeta,
    const float* __restrict__ cbp,
    const float* __restrict__ Ws,   const float* __restrict__ bs)
{
    const int b = blockIdx.x, t = threadIdx.x;
    __shared__ float h[128], h2[128], yv[128];
    __shared__ float red[4];

    // reduce split-K partials
    float s0 = 0.f, s1 = 0.f;
    const float* p = g_partial + b * 128 + t;
    for (int g = 0; g < G_; ++g) {
        s0 += p[(size_t)(g * 2 + 0) * 16384];
        s1 += p[(size_t)(g * 2 + 1) * 16384];
    }

    float hv = s0 + cbe[t];
    h[t] = hv > 0.f ? hv : expm1f(hv);           // elu
    __syncthreads();

    float a = 0.f;
    for (int k = 0; k < 128; k++) a += h[k] * cWl[k * 128 + t];
    h2[t] = a + cbl[t];
    __syncthreads();

    float gl = cbgl[t], gs = cbgs[t];
    for (int k = 0; k < 128; k++) {
        float hk = h2[k];
        gl += hk * cWgl[k * 128 + t];
        gs += hk * cWgs[k * 128 + t];
    }
    float r = s1 + cbp[t] + gl * (1.f / (1.f + expf(-gs)));

    // LayerNorm over 128 (4 warps)
    float sm = r;
    for (int o = 16; o; o >>= 1) sm += __shfl_xor_sync(~0u, sm, o);
    if ((t & 31) == 0) red[t >> 5] = sm;
    __syncthreads();
    float mean = (red[0] + red[1] + red[2] + red[3]) * (1.f / 128.f);
    float d = r - mean;
    float sq = d * d;
    for (int o = 16; o; o >>= 1) sq += __shfl_xor_sync(~0u, sq, o);
    __syncthreads();
    if ((t & 31) == 0) red[t >> 5] = sq;
    __syncthreads();
    float var = (red[0] + red[1] + red[2] + red[3]) * (1.f / 128.f);
    yv[t] = d * rsqrtf(var + 1e-3f) * cgamma[t] + cbeta[t];
    __syncthreads();

    // logits + softmax over F=32 (warp 0)
    if (t < 32) {
        float l = bs[t];
        for (int k = 0; k < 128; k++) l += yv[k] * Ws[k * 32 + t];
        float mx = l;
        for (int o = 16; o; o >>= 1) mx = fmaxf(mx, __shfl_xor_sync(~0u, mx, o));
        float e = expf(l - mx);
        float ss = e;
        for (int o = 16; o; o >>= 1) ss += __shfl_xor_sync(~0u, ss, o);
        g_wsel[b * 32 + t] = e / ss;
    }
}

// ---------------------------------------------------------------------------
// Kernel 3: per-feature GRNs + weighted combine.
// One block per batch row b (64 seq rows), loops over features; weights staged
// through SMEM, [64x128]@[128x128] stages with 4x8 microtiles.
// ---------------------------------------------------------------------------
__device__ __forceinline__ void mm64(const float* __restrict__ A,
                                     const float* __restrict__ W,
                                     int rb, int cb, float acc[4][8])
{
#pragma unroll
    for (int i = 0; i < 4; i++)
#pragma unroll
        for (int j = 0; j < 8; j++) acc[i][j] = 0.f;

#pragma unroll 4
    for (int k = 0; k < 128; k++) {
        float4 w0 = *(const float4*)(W + k * 128 + cb);
        float4 w1 = *(const float4*)(W + k * 128 + cb + 4);
        float b[8] = {w0.x, w0.y, w0.z, w0.w, w1.x, w1.y, w1.z, w1.w};
#pragma unroll
        for (int i = 0; i < 4; i++) {
            float av = A[(rb + i) * 128 + k];
#pragma unroll
            for (int j = 0; j < 8; j++) acc[i][j] += av * b[j];
        }
    }
}

__global__ __launch_bounds__(256, 1) void k_grn(
    const float* __restrict__ inputs,
    const float* __restrict__ fWe,  const float* __restrict__ fbe,
    const float* __restrict__ fWl,  const float* __restrict__ fbl,
    const float* __restrict__ fWgl, const float* __restrict__ fbgl,
    const float* __restrict__ fWgs, const float* __restrict__ fbgs,
    const float* __restrict__ fgamma, const float* __restrict__ fbeta,
    float* __restrict__ out)
{
    extern __shared__ float smem[];
    float* xs   = smem;           // [64][128] x tile, later z = x+g, in place
    float* hs   = smem + 8192;    // h, later gl
    float* h2s  = smem + 16384;   // h2
    float* accs = smem + 24576;   // output accumulator
    float* Wsm  = smem + 32768;   // [128][128] staged weight

    const int t  = threadIdx.x;
    const int tx = t & 15, ty = t >> 4;
    const int rb = ty * 4, cb = tx * 8;
    const int r0 = blockIdx.x * 64;      // rows r0..r0+63 all share b = blockIdx.x
    const int wid = t >> 5, lane = t & 31;

    for (int i = t; i < 8192; i += 256) accs[i] = 0.f;

    for (int f = 0; f < F_; ++f) {
        __syncthreads();
        // load x tile + We
        for (int i = t * 4; i < 8192; i += 1024) {
            int r = i >> 7, dcol = i & 127;
            *(float4*)(xs + i) =
                *(const float4*)(inputs + (long)(r0 + r) * 4096 + f * 128 + dcol);
        }
        {
            const float* Wg = fWe + (long)f * 16384;
            for (int i = t * 4; i < 16384; i += 1024)
                *(float4*)(Wsm + i) = *(const float4*)(Wg + i);
        }
        __syncthreads();

        // stage 1: hs = elu(xs @ We + fbe)
        {
            float acc[4][8];
            mm64(xs, Wsm, rb, cb, acc);
            const float* bias = fbe + f * 128;
#pragma unroll
            for (int i = 0; i < 4; i++)
#pragma unroll
                for (int j = 0; j < 8; j++) {
                    float v = acc[i][j] + bias[cb + j];
                    hs[(rb + i) * 128 + cb + j] = v > 0.f ? v : expm1f(v);
                }
        }
        __syncthreads();
        {
            const float* Wg = fWl + (long)f * 16384;
            for (int i = t * 4; i < 16384; i += 1024)
                *(float4*)(Wsm + i) = *(const float4*)(Wg + i);
        }
        __syncthreads();

        // stage 2: h2s = hs @ Wl + fbl
        {
            float acc[4][8];
            mm64(hs, Wsm, rb, cb, acc);
            const float* bias = fbl + f * 128;
#pragma unroll
            for (int i = 0; i < 4; i++)
#pragma unroll
                for (int j = 0; j < 8; j++)
                    h2s[(rb + i) * 128 + cb + j] = acc[i][j] + bias[cb + j];
        }
        __syncthreads();
        {
            const float* Wg = fWgl + (long)f * 16384;
            for (int i = t * 4; i < 16384; i += 1024)
                *(float4*)(Wsm + i) = *(const float4*)(Wg + i);
        }
        __syncthreads();

        // stage 3: hs = h2s @ Wgl + fbgl   (gl)
        {
            float acc[4][8];
            mm64(h2s, Wsm, rb, cb, acc);
            const float* bias = fbgl + f * 128;
#pragma unroll
            for (int i = 0; i < 4; i++)
#pragma unroll
                for (int j = 0; j < 8; j++)
                    hs[(rb + i) * 128 + cb + j] = acc[i][j] + bias[cb + j];
        }
        __syncthreads();
        {
            const float* Wg = fWgs + (long)f * 16384;
            for (int i = t * 4; i < 16384; i += 1024)
                *(float4*)(Wsm + i) = *(const float4*)(Wg + i);
        }
        __syncthreads();

        // stage 4: gs = h2s @ Wgs + fbgs ; xs += gl * sigmoid(gs)  (z = x + g)
        {
            float acc[4][8];
            mm64(h2s, Wsm, rb, cb, acc);
            const float* bias = fbgs + f * 128;
#pragma unroll
            for (int i = 0; i < 4; i++)
#pragma unroll
                for (int j = 0; j < 8; j++) {
                    float gsv = acc[i][j] + bias[cb + j];
                    float sig = 1.f / (1.f + expf(-gsv));
                    int idx = (rb + i) * 128 + cb + j;
                    xs[idx] += hs[idx] * sig;
                }
        }
        __syncthreads();

        // LayerNorm per row + weighted accumulate (one warp per row, 8 rows apart)
        {
            float wf = g_wsel[blockIdx.x * 32 + f];
            const float* gam = fgamma + f * 128;
            const float* bet = fbeta + f * 128;
            for (int r = wid; r < 64; r += 8) {
                float z0 = xs[r * 128 + lane];
                float z1 = xs[r * 128 + lane + 32];
                float z2 = xs[r * 128 + lane + 64];
                float z3 = xs[r * 128 + lane + 96];
                float s = z0 + z1 + z2 + z3;
                for (int o = 16; o; o >>= 1) s += __shfl_xor_sync(~0u, s, o);
                float mean = s * (1.f / 128.f);
                float d0 = z0 - mean, d1 = z1 - mean, d2 = z2 - mean, d3 = z3 - mean;
                float sq = d0 * d0 + d1 * d1 + d2 * d2 + d3 * d3;
                for (int o = 16; o; o >>= 1) sq += __shfl_xor_sync(~0u, sq, o);
                float rstd = rsqrtf(sq * (1.f / 128.f) + 1e-3f);
                accs[r * 128 + lane]      += wf * (d0 * rstd * gam[lane]      + bet[lane]);
                accs[r * 128 + lane + 32] += wf * (d1 * rstd * gam[lane + 32] + bet[lane + 32]);
                accs[r * 128 + lane + 64] += wf * (d2 * rstd * gam[lane + 64] + bet[lane + 64]);
                accs[r * 128 + lane + 96] += wf * (d3 * rstd * gam[lane + 96] + bet[lane + 96]);
            }
        }
    }

    __syncthreads();
    for (int i = t * 4; i < 8192; i += 1024)
        *(float4*)(out + (long)r0 * 128 + i) = *(float4*)(accs + i);
}

// ---------------------------------------------------------------------------
extern "C" void kernel_launch(void* const* d_in, const int* in_sizes, int n_in,
                              void* d_out, int out_size)
{
    const float* inputs = (const float*)d_in[0];
    const float* stat   = (const float*)d_in[1];
    const float* cWe    = (const float*)d_in[2];
    const float* cbe    = (const float*)d_in[3];
    const float* cWl    = (const float*)d_in[4];
    const float* cbl    = (const float*)d_in[5];
    const float* cWgl   = (const float*)d_in[6];
    const float* cbgl   = (const float*)d_in[7];
    const float* cWgs   = (const float*)d_in[8];
    const float* cbgs   = (const float*)d_in[9];
    const float* cgamma = (const float*)d_in[10];
    const float* cbeta  = (const float*)d_in[11];
    const float* cWp    = (const float*)d_in[12];
    const float* cbp    = (const float*)d_in[13];
    const float* Ws     = (const float*)d_in[14];
    const float* bs     = (const float*)d_in[15];
    const float* fWe    = (const float*)d_in[16];
    const float* fbe    = (const float*)d_in[17];
    const float* fWl    = (const float*)d_in[18];
    const float* fbl    = (const float*)d_in[19];
    const float* fWgl   = (const float*)d_in[20];
    const float* fbgl   = (const float*)d_in[21];
    const float* fWgs   = (const float*)d_in[22];
    const float* fbgs   = (const float*)d_in[23];
    const float* fgamma = (const float*)d_in[24];
    const float* fbeta  = (const float*)d_in[25];
    float* out = (float*)d_out;

    cudaFuncSetAttribute(k_grn, cudaFuncAttributeMaxDynamicSharedMemorySize, 196608);

    k_biggemm<<<dim3(G_, 2), 256>>>(inputs, stat, cWe, cWp);
    k_select<<<128, 128>>>(cbe, cWl, cbl, cWgl, cbgl, cWgs, cbgs,
                           cgamma, cbeta, cbp, Ws, bs);
    k_grn<<<128, 256, 196608>>>(inputs, fWe, fbe, fWl, fbl, fWgl, fbgl,
                                fWgs, fbgs, fgamma, fbeta, out);
}

// round 3
// speedup vs baseline: 1.0008x; 1.0008x over previous
#include <cuda_runtime.h>
#include <math.h>

#define B_   128
#define S_   64
#define F_   32
#define D_   128
#define U_   128
#define DS_  128
#define SFD  262144          // S*F*D
#define NTILES 2049          // DIN / 128
#define G_   296             // split-K groups for big GEMM (2 exact waves at 2 blk/SM)

// deterministic split-K scratch: [G_][2][128][128]
__device__ float g_partial[(size_t)G_ * 2 * 128 * 128];
__device__ float g_wsel[B_ * F_];

// ---------------------------------------------------------------------------
// Kernel 1: C[which] = v @ W(which), split-K over 128-wide tiles, 8x8 microtile
// v[b,k] = inputs[b*SFD + k] for k < SFD, else static[b*128 + (k-SFD)]
// ---------------------------------------------------------------------------
__global__ __launch_bounds__(256, 2) void k_biggemm(
    const float* __restrict__ inputs, const float* __restrict__ stat,
    const float* __restrict__ cWe, const float* __restrict__ cWp)
{
    const int g = blockIdx.x, which = blockIdx.y;
    const float* __restrict__ W = which ? cWp : cWe;

    __shared__ float As[8][128];
    __shared__ float Bs[8][128];

    float acc[8][8];
#pragma unroll
    for (int i = 0; i < 8; i++)
#pragma unroll
        for (int j = 0; j < 8; j++) acc[i][j] = 0.f;

    const int t  = threadIdx.x;
    const int tx = t & 15, ty = t >> 4;
    const int lm = t >> 1;          // A-load row (0..127)
    const int lc = (t & 1) * 4;     // A-load col offset within 8
    const int bk = t >> 5;          // B-load k row (0..7)
    const int bn = (t & 31) * 4;    // B-load col

    for (int tile = g; tile < NTILES; tile += G_) {
        const float* vb; long vstr;
        if (tile < 2048) { vb = inputs + (long)tile * 128; vstr = SFD; }
        else             { vb = stat;                      vstr = DS_; }
        const float* Wb = W + (long)tile * 128 * 128;

        for (int kk = 0; kk < 128; kk += 8) {
            float4 av = *(const float4*)(vb + (long)lm * vstr + kk + lc);
            float4 bv = *(const float4*)(Wb + (kk + bk) * 128 + bn);
            __syncthreads();   // protect previous compute's smem reads
            As[lc + 0][lm] = av.x; As[lc + 1][lm] = av.y;
            As[lc + 2][lm] = av.z; As[lc + 3][lm] = av.w;
            *(float4*)(&Bs[bk][bn]) = bv;
            __syncthreads();
#pragma unroll
            for (int k = 0; k < 8; k++) {
                float4 a0 = *(const float4*)(&As[k][ty * 8]);
                float4 a1 = *(const float4*)(&As[k][ty * 8 + 4]);
                float4 b0 = *(const float4*)(&Bs[k][tx * 8]);
                float4 b1 = *(const float4*)(&Bs[k][tx * 8 + 4]);
                float a[8] = {a0.x, a0.y, a0.z, a0.w, a1.x, a1.y, a1.z, a1.w};
                float b[8] = {b0.x, b0.y, b0.z, b0.w, b1.x, b1.y, b1.z, b1.w};
#pragma unroll
                for (int i = 0; i < 8; i++)
#pragma unroll
                    for (int j = 0; j < 8; j++) acc[i][j] += a[i] * b[j];
            }
        }
    }

    float* dst = g_partial + ((long)g * 2 + which) * 16384;
#pragma unroll
    for (int i = 0; i < 8; i++)
#pragma unroll
        for (int j = 0; j < 8; j += 4) {
            float4 v4 = make_float4(acc[i][j], acc[i][j+1], acc[i][j+2], acc[i][j+3]);
            *(float4*)(dst + (ty * 8 + i) * 128 + tx * 8 + j) = v4;
        }
}

// ---------------------------------------------------------------------------
// Kernel 2: selection head. One block per batch row, 128 threads.
// Reduces split-K partials, runs grn_concat + softmax dense -> g_wsel[B,F].
// ---------------------------------------------------------------------------
__global__ __launch_bounds__(128) void k_select(
    const float* __restrict__ cbe,
    const float* __restrict__ cWl,  const float* __restrict__ cbl,
    const float* __restrict__ cWgl, const float* __restrict__ cbgl,
    const float* __restrict__ cWgs, const float* __restrict__ cbgs,
    const float* __restrict__ cgamma, const float* __restrict__ cbeta,
    const float* __restrict__ cbp,
    const float* __restrict__ Ws,   const float* __restrict__ bs)
{
    const int b = blockIdx.x, t = threadIdx.x;
    __shared__ float h[128], h2[128], yv[128];
    __shared__ float red[4];

    // reduce split-K partials
    float s0 = 0.f, s1 = 0.f;
    const float* p = g_partial + b * 128 + t;
    for (int g = 0; g < G_; ++g) {
        s0 += p[(size_t)(g * 2 + 0) * 16384];
        s1 += p[(size_t)(g * 2 + 1) * 16384];
    }

    float hv = s0 + cbe[t];
    h[t] = hv > 0.f ? hv : expm1f(hv);           // elu
    __syncthreads();

    float a = 0.f;
    for (int k = 0; k < 128; k++) a += h[k] * cWl[k * 128 + t];
    h2[t] = a + cbl[t];
    __syncthreads();

    float gl = cbgl[t], gs = cbgs[t];
    for (int k = 0; k < 128; k++) {
        float hk = h2[k];
        gl += hk * cWgl[k * 128 + t];
        gs += hk * cWgs[k * 128 + t];
    }
    float r = s1 + cbp[t] + gl * (1.f / (1.f + expf(-gs)));

    // LayerNorm over 128 (4 warps)
    float sm = r;
    for (int o = 16; o; o >>= 1) sm += __shfl_xor_sync(~0u, sm, o);
    if ((t & 31) == 0) red[t >> 5] = sm;
    __syncthreads();
    float mean = (red[0] + red[1] + red[2] + red[3]) * (1.f / 128.f);
    float d = r - mean;
    float sq = d * d;
    for (int o = 16; o; o >>= 1) sq += __shfl_xor_sync(~0u, sq, o);
    __syncthreads();
    if ((t & 31) == 0) red[t >> 5] = sq;
    __syncthreads();
    float var = (red[0] + red[1] + red[2] + red[3]) * (1.f / 128.f);
    yv[t] = d * rsqrtf(var + 1e-3f) * cgamma[t] + cbeta[t];
    __syncthreads();

    // logits + softmax over F=32 (warp 0)
    if (t < 32) {
        float l = bs[t];
        for (int k = 0; k < 128; k++) l += yv[k] * Ws[k * 32 + t];
        float mx = l;
        for (int o = 16; o; o >>= 1) mx = fmaxf(mx, __shfl_xor_sync(~0u, mx, o));
        float e = expf(l - mx);
        float ss = e;
        for (int o = 16; o; o >>= 1) ss += __shfl_xor_sync(~0u, ss, o);
        g_wsel[b * 32 + t] = e / ss;
    }
}

// ---------------------------------------------------------------------------
// Kernel 3: per-feature GRNs + weighted combine.
// One block per batch row b (64 seq rows), loops over features; weights staged
// through SMEM, [64x128]@[128x128] stages with 4x8 microtiles.
// ---------------------------------------------------------------------------
__device__ __forceinline__ void mm64(const float* __restrict__ A,
                                     const float* __restrict__ W,
                                     int rb, int cb, float acc[4][8])
{
#pragma unroll
    for (int i = 0; i < 4; i++)
#pragma unroll
        for (int j = 0; j < 8; j++) acc[i][j] = 0.f;

#pragma unroll 4
    for (int k = 0; k < 128; k++) {
        float4 w0 = *(const float4*)(W + k * 128 + cb);
        float4 w1 = *(const float4*)(W + k * 128 + cb + 4);
        float b[8] = {w0.x, w0.y, w0.z, w0.w, w1.x, w1.y, w1.z, w1.w};
#pragma unroll
        for (int i = 0; i < 4; i++) {
            float av = A[(rb + i) * 128 + k];
#pragma unroll
            for (int j = 0; j < 8; j++) acc[i][j] += av * b[j];
        }
    }
}

__global__ __launch_bounds__(256, 1) void k_grn(
    const float* __restrict__ inputs,
    const float* __restrict__ fWe,  const float* __restrict__ fbe,
    const float* __restrict__ fWl,  const float* __restrict__ fbl,
    const float* __restrict__ fWgl, const float* __restrict__ fbgl,
    const float* __restrict__ fWgs, const float* __restrict__ fbgs,
    const float* __restrict__ fgamma, const float* __restrict__ fbeta,
    float* __restrict__ out)
{
    extern __shared__ float smem[];
    float* xs   = smem;           // [64][128] x tile, later z = x+g, in place
    float* hs   = smem + 8192;    // h, later gl
    float* h2s  = smem + 16384;   // h2
    float* accs = smem + 24576;   // output accumulator
    float* Wsm  = smem + 32768;   // [128][128] staged weight

    const int t  = threadIdx.x;
    const int tx = t & 15, ty = t >> 4;
    const int rb = ty * 4, cb = tx * 8;
    const int r0 = blockIdx.x * 64;      // rows r0..r0+63 all share b = blockIdx.x
    const int wid = t >> 5, lane = t & 31;

    for (int i = t; i < 8192; i += 256) accs[i] = 0.f;

    for (int f = 0; f < F_; ++f) {
        __syncthreads();
        // load x tile + We
        for (int i = t * 4; i < 8192; i += 1024) {
            int r = i >> 7, dcol = i & 127;
            *(float4*)(xs + i) =
                *(const float4*)(inputs + (long)(r0 + r) * 4096 + f * 128 + dcol);
        }
        {
            const float* Wg = fWe + (long)f * 16384;
            for (int i = t * 4; i < 16384; i += 1024)
                *(float4*)(Wsm + i) = *(const float4*)(Wg + i);
        }
        __syncthreads();

        // stage 1: hs = elu(xs @ We + fbe)
        {
            float acc[4][8];
            mm64(xs, Wsm, rb, cb, acc);
            const float* bias = fbe + f * 128;
#pragma unroll
            for (int i = 0; i < 4; i++)
#pragma unroll
                for (int j = 0; j < 8; j++) {
                    float v = acc[i][j] + bias[cb + j];
                    hs[(rb + i) * 128 + cb + j] = v > 0.f ? v : expm1f(v);
                }
        }
        __syncthreads();
        {
            const float* Wg = fWl + (long)f * 16384;
            for (int i = t * 4; i < 16384; i += 1024)
                *(float4*)(Wsm + i) = *(const float4*)(Wg + i);
        }
        __syncthreads();

        // stage 2: h2s = hs @ Wl + fbl
        {
            float acc[4][8];
            mm64(hs, Wsm, rb, cb, acc);
            const float* bias = fbl + f * 128;
#pragma unroll
            for (int i = 0; i < 4; i++)
#pragma unroll
                for (int j = 0; j < 8; j++)
                    h2s[(rb + i) * 128 + cb + j] = acc[i][j] + bias[cb + j];
        }
        __syncthreads();
        {
            const float* Wg = fWgl + (long)f * 16384;
            for (int i = t * 4; i < 16384; i += 1024)
                *(float4*)(Wsm + i) = *(const float4*)(Wg + i);
        }
        __syncthreads();

        // stage 3: hs = h2s @ Wgl + fbgl   (gl)
        {
            float acc[4][8];
            mm64(h2s, Wsm, rb, cb, acc);
            const float* bias = fbgl + f * 128;
#pragma unroll
            for (int i = 0; i < 4; i++)
#pragma unroll
                for (int j = 0; j < 8; j++)
                    hs[(rb + i) * 128 + cb + j] = acc[i][j] + bias[cb + j];
        }
        __syncthreads();
        {
            const float* Wg = fWgs + (long)f * 16384;
            for (int i = t * 4; i < 16384; i += 1024)
                *(float4*)(Wsm + i) = *(const float4*)(Wg + i);
        }
        __syncthreads();

        // stage 4: gs = h2s @ Wgs + fbgs ; xs += gl * sigmoid(gs)  (z = x + g)
        {
            float acc[4][8];
            mm64(h2s, Wsm, rb, cb, acc);
            const float* bias = fbgs + f * 128;
#pragma unroll
            for (int i = 0; i < 4; i++)
#pragma unroll
                for (int j = 0; j < 8; j++) {
                    float gsv = acc[i][j] + bias[cb + j];
                    float sig = 1.f / (1.f + expf(-gsv));
                    int idx = (rb + i) * 128 + cb + j;
                    xs[idx] += hs[idx] * sig;
                }
        }
        __syncthreads();

        // LayerNorm per row + weighted accumulate (one warp per row, 8 rows apart)
        {
            float wf = g_wsel[blockIdx.x * 32 + f];
            const float* gam = fgamma + f * 128;
            const float* bet = fbeta + f * 128;
            for (int r = wid; r < 64; r += 8) {
                float z0 = xs[r * 128 + lane];
                float z1 = xs[r * 128 + lane + 32];
                float z2 = xs[r * 128 + lane + 64];
                float z3 = xs[r * 128 + lane + 96];
                float s = z0 + z1 + z2 + z3;
                for (int o = 16; o; o >>= 1) s += __shfl_xor_sync(~0u, s, o);
                float mean = s * (1.f / 128.f);
                float d0 = z0 - mean, d1 = z1 - mean, d2 = z2 - mean, d3 = z3 - mean;
                float sq = d0 * d0 + d1 * d1 + d2 * d2 + d3 * d3;
                for (int o = 16; o; o >>= 1) sq += __shfl_xor_sync(~0u, sq, o);
                float rstd = rsqrtf(sq * (1.f / 128.f) + 1e-3f);
                accs[r * 128 + lane]      += wf * (d0 * rstd * gam[lane]      + bet[lane]);
                accs[r * 128 + lane + 32] += wf * (d1 * rstd * gam[lane + 32] + bet[lane + 32]);
                accs[r * 128 + lane + 64] += wf * (d2 * rstd * gam[lane + 64] + bet[lane + 64]);
                accs[r * 128 + lane + 96] += wf * (d3 * rstd * gam[lane + 96] + bet[lane + 96]);
            }
        }
    }

    __syncthreads();
    for (int i = t * 4; i < 8192; i += 1024)
        *(float4*)(out + (long)r0 * 128 + i) = *(float4*)(accs + i);
}

// ---------------------------------------------------------------------------
extern "C" void kernel_launch(void* const* d_in, const int* in_sizes, int n_in,
                              void* d_out, int out_size)
{
    const float* inputs = (const float*)d_in[0];
    const float* stat   = (const float*)d_in[1];
    const float* cWe    = (const float*)d_in[2];
    const float* cbe    = (const float*)d_in[3];
    const float* cWl    = (const float*)d_in[4];
    const float* cbl    = (const float*)d_in[5];
    const float* cWgl   = (const float*)d_in[6];
    const float* cbgl   = (const float*)d_in[7];
    const float* cWgs   = (const float*)d_in[8];
    const float* cbgs   = (const float*)d_in[9];
    const float* cgamma = (const float*)d_in[10];
    const float* cbeta  = (const float*)d_in[11];
    const float* cWp    = (const float*)d_in[12];
    const float* cbp    = (const float*)d_in[13];
    const float* Ws     = (const float*)d_in[14];
    const float* bs     = (const float*)d_in[15];
    const float* fWe    = (const float*)d_in[16];
    const float* fbe    = (const float*)d_in[17];
    const float* fWl    = (const float*)d_in[18];
    const float* fbl    = (const float*)d_in[19];
    const float* fWgl   = (const float*)d_in[20];
    const float* fbgl   = (const float*)d_in[21];
    const float* fWgs   = (const float*)d_in[22];
    const float* fbgs   = (const float*)d_in[23];
    const float* fgamma = (const float*)d_in[24];
    const float* fbeta  = (const float*)d_in[25];
    float* out = (float*)d_out;

    cudaFuncSetAttribute(k_grn, cudaFuncAttributeMaxDynamicSharedMemorySize, 196608);

    k_biggemm<<<dim3(G_, 2), 256>>>(inputs, stat, cWe, cWp);
    k_select<<<128, 128>>>(cbe, cWl, cbl, cWgl, cbgl, cWgs, cbgs,
                           cgamma, cbeta, cbp, Ws, bs);
    k_grn<<<128, 256, 196608>>>(inputs, fWe, fbe, fWl, fbl, fWgl, fbgl,
                                fWgs, fbgs, fgamma, fbeta, out);
}

// round 5
// speedup vs baseline: 1.4030x; 1.4019x over previous
#include <cuda_runtime.h>
#include <math.h>

#define B_   128
#define S_   64
#define F_   32
#define D_   128
#define U_   128
#define DS_  128
#define SFD  262144          // S*F*D
#define NTILES 2049          // DIN / 128
#define G_   296             // split-K groups for big GEMM

// deterministic split-K scratch: [G_][2][128][128]
__device__ float g_partial[(size_t)G_ * 2 * 128 * 128];
__device__ float g_wsel[B_ * F_];
// per-feature GRN outputs (unweighted LN results): [F][B*S][U] = 134 MB
__device__ float g_part[(size_t)F_ * B_ * S_ * U_];

// ---------------------------------------------------------------------------
// Kernel 1: C[which] = v @ W(which), split-K over 128-wide tiles, 8x8 microtile
// Register double-buffered: next chunk's LDGs issue before current compute.
// ---------------------------------------------------------------------------
__global__ __launch_bounds__(256, 2) void k_biggemm(
    const float* __restrict__ inputs, const float* __restrict__ stat,
    const float* __restrict__ cWe, const float* __restrict__ cWp)
{
    const int g = blockIdx.x, which = blockIdx.y;
    const float* __restrict__ W = which ? cWp : cWe;

    __shared__ float As[8][128];
    __shared__ float Bs[8][128];

    float acc[8][8];
#pragma unroll
    for (int i = 0; i < 8; i++)
#pragma unroll
        for (int j = 0; j < 8; j++) acc[i][j] = 0.f;

    const int t  = threadIdx.x;
    const int tx = t & 15, ty = t >> 4;
    const int lm = t >> 1;          // A-load row (0..127)
    const int lc = (t & 1) * 4;     // A-load col offset within 8
    const int bk = t >> 5;          // B-load k row (0..7)
    const int bn = (t & 31) * 4;    // B-load col

    int tile = g;
    const float* vb; long vstr; const float* Wb;
    if (tile < 2048) { vb = inputs + (long)tile * 128; vstr = SFD; }
    else             { vb = stat;                      vstr = DS_; }
    Wb = W + (long)tile * 16384;

    int kk = 0;
    float4 av = *(const float4*)(vb + (long)lm * vstr + kk + lc);
    float4 bv = *(const float4*)(Wb + (kk + bk) * 128 + bn);

    while (true) {
        __syncthreads();   // previous compute done reading smem
        As[lc + 0][lm] = av.x; As[lc + 1][lm] = av.y;
        As[lc + 2][lm] = av.z; As[lc + 3][lm] = av.w;
        *(float4*)(&Bs[bk][bn]) = bv;
        __syncthreads();

        // advance + prefetch next chunk (overlaps with compute below)
        bool more = true;
        int nkk = kk + 8, ntile = tile;
        if (nkk == 128) {
            nkk = 0; ntile = tile + G_;
            if (ntile >= NTILES) more = false;
        }
        if (more) {
            if (ntile != tile) {
                if (ntile < 2048) { vb = inputs + (long)ntile * 128; vstr = SFD; }
                else              { vb = stat;                       vstr = DS_; }
                Wb = W + (long)ntile * 16384;
            }
            av = *(const float4*)(vb + (long)lm * vstr + nkk + lc);
            bv = *(const float4*)(Wb + (nkk + bk) * 128 + bn);
        }

#pragma unroll
        for (int k = 0; k < 8; k++) {
            float4 a0 = *(const float4*)(&As[k][ty * 8]);
            float4 a1 = *(const float4*)(&As[k][ty * 8 + 4]);
            float4 b0 = *(const float4*)(&Bs[k][tx * 8]);
            float4 b1 = *(const float4*)(&Bs[k][tx * 8 + 4]);
            float a[8] = {a0.x, a0.y, a0.z, a0.w, a1.x, a1.y, a1.z, a1.w};
            float b[8] = {b0.x, b0.y, b0.z, b0.w, b1.x, b1.y, b1.z, b1.w};
#pragma unroll
            for (int i = 0; i < 8; i++)
#pragma unroll
                for (int j = 0; j < 8; j++) acc[i][j] += a[i] * b[j];
        }

        if (!more) break;
        kk = nkk; tile = ntile;
    }

    float* dst = g_partial + ((long)g * 2 + which) * 16384;
#pragma unroll
    for (int i = 0; i < 8; i++)
#pragma unroll
        for (int j = 0; j < 8; j += 4) {
            float4 v4 = make_float4(acc[i][j], acc[i][j+1], acc[i][j+2], acc[i][j+3]);
            *(float4*)(dst + (ty * 8 + i) * 128 + tx * 8 + j) = v4;
        }
}

// ---------------------------------------------------------------------------
// Kernel 2: selection head. One block per batch row, 128 threads.
// ---------------------------------------------------------------------------
__global__ __launch_bounds__(128) void k_select(
    const float* __restrict__ cbe,
    const float* __restrict__ cWl,  const float* __restrict__ cbl,
    const float* __restrict__ cWgl, const float* __restrict__ cbgl,
    const float* __restrict__ cWgs, const float* __restrict__ cbgs,
    const float* __restrict__ cgamma, const float* __restrict__ cbeta,
    const float* __restrict__ cbp,
    const float* __restrict__ Ws,   const float* __restrict__ bs)
{
    const int b = blockIdx.x, t = threadIdx.x;
    __shared__ float h[128], h2[128], yv[128];
    __shared__ float red[4];

    float s0 = 0.f, s1 = 0.f;
    const float* p = g_partial + b * 128 + t;
    for (int g = 0; g < G_; ++g) {
        s0 += p[(size_t)(g * 2 + 0) * 16384];
        s1 += p[(size_t)(g * 2 + 1) * 16384];
    }

    float hv = s0 + cbe[t];
    h[t] = hv > 0.f ? hv : expm1f(hv);           // elu
    __syncthreads();

    float a = 0.f;
    for (int k = 0; k < 128; k++) a += h[k] * cWl[k * 128 + t];
    h2[t] = a + cbl[t];
    __syncthreads();

    float gl = cbgl[t], gs = cbgs[t];
    for (int k = 0; k < 128; k++) {
        float hk = h2[k];
        gl += hk * cWgl[k * 128 + t];
        gs += hk * cWgs[k * 128 + t];
    }
    float r = s1 + cbp[t] + gl * (1.f / (1.f + expf(-gs)));

    float sm = r;
    for (int o = 16; o; o >>= 1) sm += __shfl_xor_sync(~0u, sm, o);
    if ((t & 31) == 0) red[t >> 5] = sm;
    __syncthreads();
    float mean = (red[0] + red[1] + red[2] + red[3]) * (1.f / 128.f);
    float d = r - mean;
    float sq = d * d;
    for (int o = 16; o; o >>= 1) sq += __shfl_xor_sync(~0u, sq, o);
    __syncthreads();
    if ((t & 31) == 0) red[t >> 5] = sq;
    __syncthreads();
    float var = (red[0] + red[1] + red[2] + red[3]) * (1.f / 128.f);
    yv[t] = d * rsqrtf(var + 1e-3f) * cgamma[t] + cbeta[t];
    __syncthreads();

    if (t < 32) {
        float l = bs[t];
        for (int k = 0; k < 128; k++) l += yv[k] * Ws[k * 32 + t];
        float mx = l;
        for (int o = 16; o; o >>= 1) mx = fmaxf(mx, __shfl_xor_sync(~0u, mx, o));
        float e = expf(l - mx);
        float ss = e;
        for (int o = 16; o; o >>= 1) ss += __shfl_xor_sync(~0u, ss, o);
        g_wsel[b * 32 + t] = e / ss;
    }
}

// ---------------------------------------------------------------------------
// Kernel 3: per-(batch, feature) GRN. Grid (B, F), 256 threads.
// Smem = two 32KB activation buffers + one 32KB half-weight buffer = 96 KB
// -> 2 blocks/SM. Residual x held in registers. Writes LN result to g_part[f].
// ---------------------------------------------------------------------------
__device__ __forceinline__ void mmhalf(const float* __restrict__ A,
                                       const float* __restrict__ W,
                                       int rb, int cb, int kbase, float acc[4][8])
{
#pragma unroll 2
    for (int kk = 0; kk < 64; kk += 4) {
        float4 av[4];
#pragma unroll
        for (int i = 0; i < 4; i++)
            av[i] = *(const float4*)(A + (rb + i) * 128 + kbase + kk);
#pragma unroll
        for (int dk = 0; dk < 4; dk++) {
            float4 w0 = *(const float4*)(W + (kk + dk) * 128 + cb);
            float4 w1 = *(const float4*)(W + (kk + dk) * 128 + cb + 4);
            float b[8] = {w0.x, w0.y, w0.z, w0.w, w1.x, w1.y, w1.z, w1.w};
#pragma unroll
            for (int i = 0; i < 4; i++) {
                float a = ((const float*)&av[i])[dk];
#pragma unroll
                for (int j = 0; j < 8; j++) acc[i][j] += a * b[j];
            }
        }
    }
}

// Full [64x128]@[128x128] stage: weight streamed in two 64-row halves.
__device__ __forceinline__ void gemm_stage(const float* __restrict__ A,
                                           const float* __restrict__ Wg,
                                           float* __restrict__ Wsm,
                                           int t, int rb, int cb, float acc[4][8])
{
#pragma unroll
    for (int i = 0; i < 4; i++)
#pragma unroll
        for (int j = 0; j < 8; j++) acc[i][j] = 0.f;

#pragma unroll
    for (int h = 0; h < 2; h++) {
        __syncthreads();            // Wsm free to overwrite; A writes visible
        const float* src = Wg + h * 8192;
#pragma unroll
        for (int i = t * 4; i < 8192; i += 1024)
            *(float4*)(Wsm + i) = *(const float4*)(src + i);
        __syncthreads();
        mmhalf(A, Wsm, rb, cb, h * 64, acc);
    }
}

__global__ __launch_bounds__(256, 2) void k_grn(
    const float* __restrict__ inputs,
    const float* __restrict__ fWe,  const float* __restrict__ fbe,
    const float* __restrict__ fWl,  const float* __restrict__ fbl,
    const float* __restrict__ fWgl, const float* __restrict__ fbgl,
    const float* __restrict__ fWgs, const float* __restrict__ fbgs,
    const float* __restrict__ fgamma, const float* __restrict__ fbeta)
{
    extern __shared__ float smem[];
    float* bufA = smem;            // [64][128]  x -> h2 -> z
    float* bufB = smem + 8192;     // [64][128]  h -> gl
    float* Wsm  = smem + 16384;    // [64][128]  weight half

    const int t  = threadIdx.x;
    const int tx = t & 15, ty = t >> 4;
    const int rb = ty * 4, cb = tx * 8;
    const int b = blockIdx.x, f = blockIdx.y;
    const int r0 = b * 64;
    const int wid = t >> 5, lane = t & 31;

    // load x tile into bufA
#pragma unroll
    for (int i = t * 4; i < 8192; i += 1024) {
        int r = i >> 7, c = i & 127;
        *(float4*)(bufA + i) =
            *(const float4*)(inputs + (size_t)(r0 + r) * 4096 + f * 128 + c);
    }
    __syncthreads();

    // keep residual x patch in registers (this thread's 4x8 output tile)
    float4 xr0[4], xr1[4];
#pragma unroll
    for (int i = 0; i < 4; i++) {
        xr0[i] = *(const float4*)(bufA + (rb + i) * 128 + cb);
        xr1[i] = *(const float4*)(bufA + (rb + i) * 128 + cb + 4);
    }

    float acc[4][8];

    // stage 1: h = elu(x @ We + be)   (bufA -> bufB)
    gemm_stage(bufA, fWe + (size_t)f * 16384, Wsm, t, rb, cb, acc);
    {
        const float* bias = fbe + f * 128;
        float bj[8];
#pragma unroll
        for (int j = 0; j < 8; j++) bj[j] = bias[cb + j];
#pragma unroll
        for (int i = 0; i < 4; i++) {
            float o[8];
#pragma unroll
            for (int j = 0; j < 8; j++) {
                float v = acc[i][j] + bj[j];
                o[j] = v > 0.f ? v : (__expf(v) - 1.f);
            }
            *(float4*)(bufB + (rb + i) * 128 + cb)     = make_float4(o[0], o[1], o[2], o[3]);
            *(float4*)(bufB + (rb + i) * 128 + cb + 4) = make_float4(o[4], o[5], o[6], o[7]);
        }
    }

    // stage 2: h2 = h @ Wl + bl   (bufB -> bufA; x now lives only in regs)
    gemm_stage(bufB, fWl + (size_t)f * 16384, Wsm, t, rb, cb, acc);
    {
        const float* bias = fbl + f * 128;
        float bj[8];
#pragma unroll
        for (int j = 0; j < 8; j++) bj[j] = bias[cb + j];
#pragma unroll
        for (int i = 0; i < 4; i++) {
            *(float4*)(bufA + (rb + i) * 128 + cb) =
                make_float4(acc[i][0] + bj[0], acc[i][1] + bj[1],
                            acc[i][2] + bj[2], acc[i][3] + bj[3]);
            *(float4*)(bufA + (rb + i) * 128 + cb + 4) =
                make_float4(acc[i][4] + bj[4], acc[i][5] + bj[5],
                            acc[i][6] + bj[6], acc[i][7] + bj[7]);
        }
    }

    // stage 3: gl = h2 @ Wgl + bgl   (bufA -> bufB)
    gemm_stage(bufA, fWgl + (size_t)f * 16384, Wsm, t, rb, cb, acc);
    {
        const float* bias = fbgl + f * 128;
        float bj[8];
#pragma unroll
        for (int j = 0; j < 8; j++) bj[j] = bias[cb + j];
#pragma unroll
        for (int i = 0; i < 4; i++) {
            *(float4*)(bufB + (rb + i) * 128 + cb) =
                make_float4(acc[i][0] + bj[0], acc[i][1] + bj[1],
                            acc[i][2] + bj[2], acc[i][3] + bj[3]);
            *(float4*)(bufB + (rb + i) * 128 + cb + 4) =
                make_float4(acc[i][4] + bj[4], acc[i][5] + bj[5],
                            acc[i][6] + bj[6], acc[i][7] + bj[7]);
        }
    }

    // stage 4: gs = h2 @ Wgs + bgs (regs); z = x + gl * sigmoid(gs) -> bufA
    gemm_stage(bufA, fWgs + (size_t)f * 16384, Wsm, t, rb, cb, acc);
    __syncthreads();      // all stage-4 GEMM reads of bufA (h2) complete
    {
        const float* bias = fbgs + f * 128;
        float bj[8];
#pragma unroll
        for (int j = 0; j < 8; j++) bj[j] = bias[cb + j];
#pragma unroll
        for (int i = 0; i < 4; i++) {
            int base = (rb + i) * 128 + cb;
            float4 gl0 = *(const float4*)(bufB + base);
            float4 gl1 = *(const float4*)(bufB + base + 4);
            float s[8];
#pragma unroll
            for (int j = 0; j < 8; j++) {
                float gsv = acc[i][j] + bj[j];
                s[j] = __fdividef(1.f, 1.f + __expf(-gsv));
            }
            float4 z0, z1;
            z0.x = xr0[i].x + gl0.x * s[0]; z0.y = xr0[i].y + gl0.y * s[1];
            z0.z = xr0[i].z + gl0.z * s[2]; z0.w = xr0[i].w + gl0.w * s[3];
            z1.x = xr1[i].x + gl1.x * s[4]; z1.y = xr1[i].y + gl1.y * s[5];
            z1.z = xr1[i].z + gl1.z * s[6]; z1.w = xr1[i].w + gl1.w * s[7];
            *(float4*)(bufA + base)     = z0;
            *(float4*)(bufA + base + 4) = z1;
        }
    }
    __syncthreads();

    // LayerNorm per row, write to per-feature partial buffer (unweighted)
    {
        const float* gam = fgamma + f * 128;
        const float* bet = fbeta + f * 128;
        float* dst = g_part + (size_t)f * 1048576 + (size_t)r0 * 128;
        for (int r = wid; r < 64; r += 8) {
            float z0 = bufA[r * 128 + lane];
            float z1 = bufA[r * 128 + lane + 32];
            float z2 = bufA[r * 128 + lane + 64];
            float z3 = bufA[r * 128 + lane + 96];
            float s = z0 + z1 + z2 + z3;
            for (int o = 16; o; o >>= 1) s += __shfl_xor_sync(~0u, s, o);
            float mean = s * (1.f / 128.f);
            float d0 = z0 - mean, d1 = z1 - mean, d2 = z2 - mean, d3 = z3 - mean;
            float sq = d0 * d0 + d1 * d1 + d2 * d2 + d3 * d3;
            for (int o = 16; o; o >>= 1) sq += __shfl_xor_sync(~0u, sq, o);
            float rstd = rsqrtf(sq * (1.f / 128.f) + 1e-3f);
            dst[r * 128 + lane]      = d0 * rstd * gam[lane]      + bet[lane];
            dst[r * 128 + lane + 32] = d1 * rstd * gam[lane + 32] + bet[lane + 32];
            dst[r * 128 + lane + 64] = d2 * rstd * gam[lane + 64] + bet[lane + 64];
            dst[r * 128 + lane + 96] = d3 * rstd * gam[lane + 96] + bet[lane + 96];
        }
    }
}

// ---------------------------------------------------------------------------
// Kernel 4: deterministic softmax-weighted combine over features.
// out[row, col] = sum_f w[b, f] * g_part[f][row, col]
// ---------------------------------------------------------------------------
__global__ __launch_bounds__(256) void k_combine(float* __restrict__ out)
{
    __shared__ float ws[32];
    const int b = blockIdx.x >> 3;       // 8 blocks per batch row group
    if (threadIdx.x < 32) ws[threadIdx.x] = g_wsel[b * 32 + threadIdx.x];
    __syncthreads();

    const size_t gid = (size_t)blockIdx.x * 256 + threadIdx.x;   // float4 index
    float4 acc = make_float4(0.f, 0.f, 0.f, 0.f);
#pragma unroll 8
    for (int f = 0; f < 32; f++) {
        float4 v = ((const float4*)g_part)[(size_t)f * 262144 + gid];
        float w = ws[f];
        acc.x += w * v.x; acc.y += w * v.y;
        acc.z += w * v.z; acc.w += w * v.w;
    }
    ((float4*)out)[gid] = acc;
}

// ---------------------------------------------------------------------------
extern "C" void kernel_launch(void* const* d_in, const int* in_sizes, int n_in,
                              void* d_out, int out_size)
{
    const float* inputs = (const float*)d_in[0];
    const float* stat   = (const float*)d_in[1];
    const float* cWe    = (const float*)d_in[2];
    const float* cbe    = (const float*)d_in[3];
    const float* cWl    = (const float*)d_in[4];
    const float* cbl    = (const float*)d_in[5];
    const float* cWgl   = (const float*)d_in[6];
    const float* cbgl   = (const float*)d_in[7];
    const float* cWgs   = (const float*)d_in[8];
    const float* cbgs   = (const float*)d_in[9];
    const float* cgamma = (const float*)d_in[10];
    const float* cbeta  = (const float*)d_in[11];
    const float* cWp    = (const float*)d_in[12];
    const float* cbp    = (const float*)d_in[13];
    const float* Ws     = (const float*)d_in[14];
    const float* bs     = (const float*)d_in[15];
    const float* fWe    = (const float*)d_in[16];
    const float* fbe    = (const float*)d_in[17];
    const float* fWl    = (const float*)d_in[18];
    const float* fbl    = (const float*)d_in[19];
    const float* fWgl   = (const float*)d_in[20];
    const float* fbgl   = (const float*)d_in[21];
    const float* fWgs   = (const float*)d_in[22];
    const float* fbgs   = (const float*)d_in[23];
    const float* fgamma = (const float*)d_in[24];
    const float* fbeta  = (const float*)d_in[25];
    float* out = (float*)d_out;

    cudaFuncSetAttribute(k_grn, cudaFuncAttributeMaxDynamicSharedMemorySize, 98304);

    k_biggemm<<<dim3(G_, 2), 256>>>(inputs, stat, cWe, cWp);
    k_select<<<128, 128>>>(cbe, cWl, cbl, cWgl, cbgl, cWgs, cbgs,
                           cgamma, cbeta, cbp, Ws, bs);
    k_grn<<<dim3(B_, F_), 256, 98304>>>(inputs, fWe, fbe, fWl, fbl, fWgl, fbgl,
                                        fWgs, fbgs, fgamma, fbeta);
    k_combine<<<1024, 256>>>(out);
}

// round 7
// speedup vs baseline: 1.4453x; 1.0301x over previous
#include <cuda_runtime.h>
#include <math.h>

#define B_   128
#define S_   64
#define F_   32
#define D_   128
#define U_   128
#define DS_  128
#define SFD  262144          // S*F*D
#define NTILES 2049          // DIN / 128
#define G_   296             // split-K groups for big GEMM

// deterministic split-K scratch: [G_][2][128][128]
__device__ float g_partial[(size_t)G_ * 2 * 128 * 128];
__device__ float g_wsel[B_ * F_];
// per-feature GRN outputs (unweighted LN results): [F][B*S][U] = 134 MB
__device__ float g_part[(size_t)F_ * B_ * S_ * U_];

// ---------------------------------------------------------------------------
// Packed f32x2 helpers (sm_103a FFMA2 — ptxas won't auto-fuse; PTX only)
// ---------------------------------------------------------------------------
__device__ __forceinline__ unsigned long long pack2(float x, float y) {
    unsigned long long r;
    asm("mov.b64 %0, {%1, %2};" : "=l"(r) : "f"(x), "f"(y));
    return r;
}
__device__ __forceinline__ void unpack2(unsigned long long v, float& x, float& y) {
    asm("mov.b64 {%0, %1}, %2;" : "=f"(x), "=f"(y) : "l"(v));
}
__device__ __forceinline__ unsigned long long ffma2(
    unsigned long long a, unsigned long long b, unsigned long long c) {
    unsigned long long d;
    asm("fma.rn.f32x2 %0, %1, %2, %3;" : "=l"(d) : "l"(a), "l"(b), "l"(c));
    return d;
}

// ---------------------------------------------------------------------------
// Kernel 1: C[which] = v @ W(which), split-K over 128-wide tiles, 8x8 microtile
// Register double-buffered LDGs + FFMA2 inner product.
// ---------------------------------------------------------------------------
__global__ __launch_bounds__(256, 2) void k_biggemm(
    const float* __restrict__ inputs, const float* __restrict__ stat,
    const float* __restrict__ cWe, const float* __restrict__ cWp)
{
    const int g = blockIdx.x, which = blockIdx.y;
    const float* __restrict__ W = which ? cWp : cWe;

    __shared__ __align__(16) float As[8][128];
    __shared__ __align__(16) float Bs[8][128];

    unsigned long long acc2[8][4];
#pragma unroll
    for (int i = 0; i < 8; i++)
#pragma unroll
        for (int j = 0; j < 4; j++) acc2[i][j] = 0ull;

    const int t  = threadIdx.x;
    const int tx = t & 15, ty = t >> 4;
    const int lm = t >> 1;          // A-load row (0..127)
    const int lc = (t & 1) * 4;     // A-load col offset within 8
    const int bk = t >> 5;          // B-load k row (0..7)
    const int bn = (t & 31) * 4;    // B-load col

    int tile = g;
    const float* vb; long vstr; const float* Wb;
    if (tile < 2048) { vb = inputs + (long)tile * 128; vstr = SFD; }
    else             { vb = stat;                      vstr = DS_; }
    Wb = W + (long)tile * 16384;

    int kk = 0;
    float4 av = *(const float4*)(vb + (long)lm * vstr + kk + lc);
    float4 bv = *(const float4*)(Wb + (kk + bk) * 128 + bn);

    while (true) {
        __syncthreads();   // previous compute done reading smem
        As[lc + 0][lm] = av.x; As[lc + 1][lm] = av.y;
        As[lc + 2][lm] = av.z; As[lc + 3][lm] = av.w;
        *(float4*)(&Bs[bk][bn]) = bv;
        __syncthreads();

        // advance + prefetch next chunk (overlaps with compute below)
        bool more = true;
        int nkk = kk + 8, ntile = tile;
        if (nkk == 128) {
            nkk = 0; ntile = tile + G_;
            if (ntile >= NTILES) more = false;
        }
        if (more) {
            if (ntile != tile) {
                if (ntile < 2048) { vb = inputs + (long)ntile * 128; vstr = SFD; }
                else              { vb = stat;                       vstr = DS_; }
                Wb = W + (long)ntile * 16384;
            }
            av = *(const float4*)(vb + (long)lm * vstr + nkk + lc);
            bv = *(const float4*)(Wb + (nkk + bk) * 128 + bn);
        }

#pragma unroll
        for (int k = 0; k < 8; k++) {
            float4 a0 = *(const float4*)(&As[k][ty * 8]);
            float4 a1 = *(const float4*)(&As[k][ty * 8 + 4]);
            ulonglong2 b0 = *(const ulonglong2*)(&Bs[k][tx * 8]);
            ulonglong2 b1 = *(const ulonglong2*)(&Bs[k][tx * 8 + 4]);
            unsigned long long bp[4] = {b0.x, b0.y, b1.x, b1.y};
            float a[8] = {a0.x, a0.y, a0.z, a0.w, a1.x, a1.y, a1.z, a1.w};
#pragma unroll
            for (int i = 0; i < 8; i++) {
                unsigned long long ap = pack2(a[i], a[i]);
#pragma unroll
                for (int j = 0; j < 4; j++)
                    acc2[i][j] = ffma2(ap, bp[j], acc2[i][j]);
            }
        }

        if (!more) break;
        kk = nkk; tile = ntile;
    }

    float* dst = g_partial + ((long)g * 2 + which) * 16384;
#pragma unroll
    for (int i = 0; i < 8; i++) {
        float4 v0, v1;
        unpack2(acc2[i][0], v0.x, v0.y);
        unpack2(acc2[i][1], v0.z, v0.w);
        unpack2(acc2[i][2], v1.x, v1.y);
        unpack2(acc2[i][3], v1.z, v1.w);
        *(float4*)(dst + (ty * 8 + i) * 128 + tx * 8)     = v0;
        *(float4*)(dst + (ty * 8 + i) * 128 + tx * 8 + 4) = v1;
    }
}

// ---------------------------------------------------------------------------
// Kernel 2: selection head. One block per batch row, 128 threads.
// ---------------------------------------------------------------------------
__global__ __launch_bounds__(128) void k_select(
    const float* __restrict__ cbe,
    const float* __restrict__ cWl,  const float* __restrict__ cbl,
    const float* __restrict__ cWgl, const float* __restrict__ cbgl,
    const float* __restrict__ cWgs, const float* __restrict__ cbgs,
    const float* __restrict__ cgamma, const float* __restrict__ cbeta,
    const float* __restrict__ cbp,
    const float* __restrict__ Ws,   const float* __restrict__ bs)
{
    const int b = blockIdx.x, t = threadIdx.x;
    __shared__ float h[128], h2[128], yv[128];
    __shared__ float red[4];

    float s0 = 0.f, s1 = 0.f;
    const float* p = g_partial + b * 128 + t;
    for (int g = 0; g < G_; ++g) {
        s0 += p[(size_t)(g * 2 + 0) * 16384];
        s1 += p[(size_t)(g * 2 + 1) * 16384];
    }

    float hv = s0 + cbe[t];
    h[t] = hv > 0.f ? hv : expm1f(hv);           // elu
    __syncthreads();

    float a = 0.f;
    for (int k = 0; k < 128; k++) a += h[k] * cWl[k * 128 + t];
    h2[t] = a + cbl[t];
    __syncthreads();

    float gl = cbgl[t], gs = cbgs[t];
    for (int k = 0; k < 128; k++) {
        float hk = h2[k];
        gl += hk * cWgl[k * 128 + t];
        gs += hk * cWgs[k * 128 + t];
    }
    float r = s1 + cbp[t] + gl * (1.f / (1.f + expf(-gs)));

    float sm = r;
    for (int o = 16; o; o >>= 1) sm += __shfl_xor_sync(~0u, sm, o);
    if ((t & 31) == 0) red[t >> 5] = sm;
    __syncthreads();
    float mean = (red[0] + red[1] + red[2] + red[3]) * (1.f / 128.f);
    float d = r - mean;
    float sq = d * d;
    for (int o = 16; o; o >>= 1) sq += __shfl_xor_sync(~0u, sq, o);
    __syncthreads();
    if ((t & 31) == 0) red[t >> 5] = sq;
    __syncthreads();
    float var = (red[0] + red[1] + red[2] + red[3]) * (1.f / 128.f);
    yv[t] = d * rsqrtf(var + 1e-3f) * cgamma[t] + cbeta[t];
    __syncthreads();

    if (t < 32) {
        float l = bs[t];
        for (int k = 0; k < 128; k++) l += yv[k] * Ws[k * 32 + t];
        float mx = l;
        for (int o = 16; o; o >>= 1) mx = fmaxf(mx, __shfl_xor_sync(~0u, mx, o));
        float e = expf(l - mx);
        float ss = e;
        for (int o = 16; o; o >>= 1) ss += __shfl_xor_sync(~0u, ss, o);
        g_wsel[b * 32 + t] = e / ss;
    }
}

// ---------------------------------------------------------------------------
// Kernel 3: per-(batch, feature) GRN. Grid (B, F), 256 threads, 96 KB smem
// -> 2 blocks/SM. FFMA2 inner product. Residual x in registers.
// ---------------------------------------------------------------------------
__device__ __forceinline__ void mmhalf(const float* __restrict__ A,
                                       const float* __restrict__ W,
                                       int rb, int cb, int kbase,
                                       unsigned long long acc2[4][4])
{
#pragma unroll 2
    for (int kk = 0; kk < 64; kk += 4) {
        float4 av[4];
#pragma unroll
        for (int i = 0; i < 4; i++)
            av[i] = *(const float4*)(A + (rb + i) * 128 + kbase + kk);
#pragma unroll
        for (int dk = 0; dk < 4; dk++) {
            ulonglong2 w0 = *(const ulonglong2*)(W + (kk + dk) * 128 + cb);
            ulonglong2 w1 = *(const ulonglong2*)(W + (kk + dk) * 128 + cb + 4);
            unsigned long long bp[4] = {w0.x, w0.y, w1.x, w1.y};
#pragma unroll
            for (int i = 0; i < 4; i++) {
                float a = ((const float*)&av[i])[dk];
                unsigned long long ap = pack2(a, a);
#pragma unroll
                for (int j = 0; j < 4; j++)
                    acc2[i][j] = ffma2(ap, bp[j], acc2[i][j]);
            }
        }
    }
}

// Full [64x128]@[128x128] stage: weight streamed in two 64-row halves.
__device__ __forceinline__ void gemm_stage(const float* __restrict__ A,
                                           const float* __restrict__ Wg,
                                           float* __restrict__ Wsm,
                                           int t, int rb, int cb, float acc[4][8])
{
    unsigned long long acc2[4][4];
#pragma unroll
    for (int i = 0; i < 4; i++)
#pragma unroll
        for (int j = 0; j < 4; j++) acc2[i][j] = 0ull;

#pragma unroll
    for (int h = 0; h < 2; h++) {
        __syncthreads();            // Wsm free to overwrite; A writes visible
        const float* src = Wg + h * 8192;
#pragma unroll
        for (int i = t * 4; i < 8192; i += 1024)
            *(float4*)(Wsm + i) = *(const float4*)(src + i);
        __syncthreads();
        mmhalf(A, Wsm, rb, cb, h * 64, acc2);
    }

#pragma unroll
    for (int i = 0; i < 4; i++) {
        unpack2(acc2[i][0], acc[i][0], acc[i][1]);
        unpack2(acc2[i][1], acc[i][2], acc[i][3]);
        unpack2(acc2[i][2], acc[i][4], acc[i][5]);
        unpack2(acc2[i][3], acc[i][6], acc[i][7]);
    }
}

__global__ __launch_bounds__(256, 2) void k_grn(
    const float* __restrict__ inputs,
    const float* __restrict__ fWe,  const float* __restrict__ fbe,
    const float* __restrict__ fWl,  const float* __restrict__ fbl,
    const float* __restrict__ fWgl, const float* __restrict__ fbgl,
    const float* __restrict__ fWgs, const float* __restrict__ fbgs,
    const float* __restrict__ fgamma, const float* __restrict__ fbeta)
{
    extern __shared__ float smem[];
    float* bufA = smem;            // [64][128]  x -> h2 -> z
    float* bufB = smem + 8192;     // [64][128]  h -> gl
    float* Wsm  = smem + 16384;    // [64][128]  weight half

    const int t  = threadIdx.x;
    const int tx = t & 15, ty = t >> 4;
    const int rb = ty * 4, cb = tx * 8;
    const int b = blockIdx.x, f = blockIdx.y;
    const int r0 = b * 64;
    const int wid = t >> 5, lane = t & 31;

    // load x tile into bufA
#pragma unroll
    for (int i = t * 4; i < 8192; i += 1024) {
        int r = i >> 7, c = i & 127;
        *(float4*)(bufA + i) =
            *(const float4*)(inputs + (size_t)(r0 + r) * 4096 + f * 128 + c);
    }
    __syncthreads();

    // keep residual x patch in registers (this thread's 4x8 output tile)
    float4 xr0[4], xr1[4];
#pragma unroll
    for (int i = 0; i < 4; i++) {
        xr0[i] = *(const float4*)(bufA + (rb + i) * 128 + cb);
        xr1[i] = *(const float4*)(bufA + (rb + i) * 128 + cb + 4);
    }

    float acc[4][8];

    // stage 1: h = elu(x @ We + be)   (bufA -> bufB)
    gemm_stage(bufA, fWe + (size_t)f * 16384, Wsm, t, rb, cb, acc);
    {
        const float* bias = fbe + f * 128;
        float bj[8];
#pragma unroll
        for (int j = 0; j < 8; j++) bj[j] = bias[cb + j];
#pragma unroll
        for (int i = 0; i < 4; i++) {
            float o[8];
#pragma unroll
            for (int j = 0; j < 8; j++) {
                float v = acc[i][j] + bj[j];
                o[j] = v > 0.f ? v : (__expf(v) - 1.f);
            }
            *(float4*)(bufB + (rb + i) * 128 + cb)     = make_float4(o[0], o[1], o[2], o[3]);
            *(float4*)(bufB + (rb + i) * 128 + cb + 4) = make_float4(o[4], o[5], o[6], o[7]);
        }
    }

    // stage 2: h2 = h @ Wl + bl   (bufB -> bufA; x now lives only in regs)
    gemm_stage(bufB, fWl + (size_t)f * 16384, Wsm, t, rb, cb, acc);
    {
        const float* bias = fbl + f * 128;
        float bj[8];
#pragma unroll
        for (int j = 0; j < 8; j++) bj[j] = bias[cb + j];
#pragma unroll
        for (int i = 0; i < 4; i++) {
            *(float4*)(bufA + (rb + i) * 128 + cb) =
                make_float4(acc[i][0] + bj[0], acc[i][1] + bj[1],
                            acc[i][2] + bj[2], acc[i][3] + bj[3]);
            *(float4*)(bufA + (rb + i) * 128 + cb + 4) =
                make_float4(acc[i][4] + bj[4], acc[i][5] + bj[5],
                            acc[i][6] + bj[6], acc[i][7] + bj[7]);
        }
    }

    // stage 3: gl = h2 @ Wgl + bgl   (bufA -> bufB)
    gemm_stage(bufA, fWgl + (size_t)f * 16384, Wsm, t, rb, cb, acc);
    {
        const float* bias = fbgl + f * 128;
        float bj[8];
#pragma unroll
        for (int j = 0; j < 8; j++) bj[j] = bias[cb + j];
#pragma unroll
        for (int i = 0; i < 4; i++) {
            *(float4*)(bufB + (rb + i) * 128 + cb) =
                make_float4(acc[i][0] + bj[0], acc[i][1] + bj[1],
                            acc[i][2] + bj[2], acc[i][3] + bj[3]);
            *(float4*)(bufB + (rb + i) * 128 + cb + 4) =
                make_float4(acc[i][4] + bj[4], acc[i][5] + bj[5],
                            acc[i][6] + bj[6], acc[i][7] + bj[7]);
        }
    }

    // stage 4: gs = h2 @ Wgs + bgs (regs); z = x + gl * sigmoid(gs) -> bufA
    gemm_stage(bufA, fWgs + (size_t)f * 16384, Wsm, t, rb, cb, acc);
    __syncthreads();      // all stage-4 GEMM reads of bufA (h2) complete
    {
        const float* bias = fbgs + f * 128;
        float bj[8];
#pragma unroll
        for (int j = 0; j < 8; j++) bj[j] = bias[cb + j];
#pragma unroll
        for (int i = 0; i < 4; i++) {
            int base = (rb + i) * 128 + cb;
            float4 gl0 = *(const float4*)(bufB + base);
            float4 gl1 = *(const float4*)(bufB + base + 4);
            float s[8];
#pragma unroll
            for (int j = 0; j < 8; j++) {
                float gsv = acc[i][j] + bj[j];
                s[j] = __fdividef(1.f, 1.f + __expf(-gsv));
            }
            float4 z0, z1;
            z0.x = xr0[i].x + gl0.x * s[0]; z0.y = xr0[i].y + gl0.y * s[1];
            z0.z = xr0[i].z + gl0.z * s[2]; z0.w = xr0[i].w + gl0.w * s[3];
            z1.x = xr1[i].x + gl1.x * s[4]; z1.y = xr1[i].y + gl1.y * s[5];
            z1.z = xr1[i].z + gl1.z * s[6]; z1.w = xr1[i].w + gl1.w * s[7];
            *(float4*)(bufA + base)     = z0;
            *(float4*)(bufA + base + 4) = z1;
        }
    }
    __syncthreads();

    // LayerNorm per row, write to per-feature partial buffer (unweighted)
    {
        const float* gam = fgamma + f * 128;
        const float* bet = fbeta + f * 128;
        float* dst = g_part + (size_t)f * 1048576 + (size_t)r0 * 128;
        for (int r = wid; r < 64; r += 8) {
            float z0 = bufA[r * 128 + lane];
            float z1 = bufA[r * 128 + lane + 32];
            float z2 = bufA[r * 128 + lane + 64];
            float z3 = bufA[r * 128 + lane + 96];
            float s = z0 + z1 + z2 + z3;
            for (int o = 16; o; o >>= 1) s += __shfl_xor_sync(~0u, s, o);
            float mean = s * (1.f / 128.f);
            float d0 = z0 - mean, d1 = z1 - mean, d2 = z2 - mean, d3 = z3 - mean;
            float sq = d0 * d0 + d1 * d1 + d2 * d2 + d3 * d3;
            for (int o = 16; o; o >>= 1) sq += __shfl_xor_sync(~0u, sq, o);
            float rstd = rsqrtf(sq * (1.f / 128.f) + 1e-3f);
            dst[r * 128 + lane]      = d0 * rstd * gam[lane]      + bet[lane];
            dst[r * 128 + lane + 32] = d1 * rstd * gam[lane + 32] + bet[lane + 32];
            dst[r * 128 + lane + 64] = d2 * rstd * gam[lane + 64] + bet[lane + 64];
            dst[r * 128 + lane + 96] = d3 * rstd * gam[lane + 96] + bet[lane + 96];
        }
    }
}

// ---------------------------------------------------------------------------
// Kernel 4: deterministic softmax-weighted combine over features.
// ---------------------------------------------------------------------------
__global__ __launch_bounds__(256) void k_combine(float* __restrict__ out)
{
    __shared__ float ws[32];
    const int b = blockIdx.x >> 3;       // 8 blocks per batch row group
    if (threadIdx.x < 32) ws[threadIdx.x] = g_wsel[b * 32 + threadIdx.x];
    __syncthreads();

    const size_t gid = (size_t)blockIdx.x * 256 + threadIdx.x;   // float4 index
    float4 acc = make_float4(0.f, 0.f, 0.f, 0.f);
#pragma unroll 8
    for (int f = 0; f < 32; f++) {
        float4 v = ((const float4*)g_part)[(size_t)f * 262144 + gid];
        float w = ws[f];
        acc.x += w * v.x; acc.y += w * v.y;
        acc.z += w * v.z; acc.w += w * v.w;
    }
    ((float4*)out)[gid] = acc;
}

// ---------------------------------------------------------------------------
extern "C" void kernel_launch(void* const* d_in, const int* in_sizes, int n_in,
                              void* d_out, int out_size)
{
    const float* inputs = (const float*)d_in[0];
    const float* stat   = (const float*)d_in[1];
    const float* cWe    = (const float*)d_in[2];
    const float* cbe    = (const float*)d_in[3];
    const float* cWl    = (const float*)d_in[4];
    const float* cbl    = (const float*)d_in[5];
    const float* cWgl   = (const float*)d_in[6];
    const float* cbgl   = (const float*)d_in[7];
    const float* cWgs   = (const float*)d_in[8];
    const float* cbgs   = (const float*)d_in[9];
    const float* cgamma = (const float*)d_in[10];
    const float* cbeta  = (const float*)d_in[11];
    const float* cWp    = (const float*)d_in[12];
    const float* cbp    = (const float*)d_in[13];
    const float* Ws     = (const float*)d_in[14];
    const float* bs     = (const float*)d_in[15];
    const float* fWe    = (const float*)d_in[16];
    const float* fbe    = (const float*)d_in[17];
    const float* fWl    = (const float*)d_in[18];
    const float* fbl    = (const float*)d_in[19];
    const float* fWgl   = (const float*)d_in[20];
    const float* fbgl   = (const float*)d_in[21];
    const float* fWgs   = (const float*)d_in[22];
    const float* fbgs   = (const float*)d_in[23];
    const float* fgamma = (const float*)d_in[24];
    const float* fbeta  = (const float*)d_in[25];
    float* out = (float*)d_out;

    cudaFuncSetAttribute(k_grn, cudaFuncAttributeMaxDynamicSharedMemorySize, 98304);

    k_biggemm<<<dim3(G_, 2), 256>>>(inputs, stat, cWe, cWp);
    k_select<<<128, 128>>>(cbe, cWl, cbl, cWgl, cbgl, cWgs, cbgs,
                           cgamma, cbeta, cbp, Ws, bs);
    k_grn<<<dim3(B_, F_), 256, 98304>>>(inputs, fWe, fbe, fWl, fbl, fWgl, fbgl,
                                        fWgs, fbgs, fgamma, fbeta);
    k_combine<<<1024, 256>>>(out);
}

// round 9
// speedup vs baseline: 1.4479x; 1.0018x over previous
#include <cuda_runtime.h>
#include <math.h>

#define B_   128
#define S_   64
#define F_   32
#define D_   128
#define U_   128
#define DS_  128
#define SFD  262144          // S*F*D
#define NTILES 2049          // DIN / 128
#define G_   296             // split-K groups for big GEMM

// deterministic split-K scratch: [G_][2][128][128]
__device__ float g_partial[(size_t)G_ * 2 * 128 * 128];
__device__ float g_wsel[B_ * F_];
// per-feature GRN outputs (unweighted LN results): [F][B*S][U] = 134 MB
__device__ float g_part[(size_t)F_ * B_ * S_ * U_];

// ---------------------------------------------------------------------------
// Packed f32x2 helpers (sm_103a FFMA2 — ptxas won't auto-fuse; PTX only)
// ---------------------------------------------------------------------------
__device__ __forceinline__ unsigned long long pack2(float x, float y) {
    unsigned long long r;
    asm("mov.b64 %0, {%1, %2};" : "=l"(r) : "f"(x), "f"(y));
    return r;
}
__device__ __forceinline__ void unpack2(unsigned long long v, float& x, float& y) {
    asm("mov.b64 {%0, %1}, %2;" : "=f"(x), "=f"(y) : "l"(v));
}
__device__ __forceinline__ unsigned long long ffma2(
    unsigned long long a, unsigned long long b, unsigned long long c) {
    unsigned long long d;
    asm("fma.rn.f32x2 %0, %1, %2, %3;" : "=l"(d) : "l"(a), "l"(b), "l"(c));
    return d;
}

// ---------------------------------------------------------------------------
// Kernel 1: C[which] = v @ W(which), split-K over 128-wide tiles, 8x8 microtile
// Register double-buffered LDGs + FFMA2 inner product.
// ---------------------------------------------------------------------------
__global__ __launch_bounds__(256, 2) void k_biggemm(
    const float* __restrict__ inputs, const float* __restrict__ stat,
    const float* __restrict__ cWe, const float* __restrict__ cWp)
{
    const int g = blockIdx.x, which = blockIdx.y;
    const float* __restrict__ W = which ? cWp : cWe;

    __shared__ __align__(16) float As[8][128];
    __shared__ __align__(16) float Bs[8][128];

    unsigned long long acc2[8][4];
#pragma unroll
    for (int i = 0; i < 8; i++)
#pragma unroll
        for (int j = 0; j < 4; j++) acc2[i][j] = 0ull;

    const int t  = threadIdx.x;
    const int tx = t & 15, ty = t >> 4;
    const int lm = t >> 1;          // A-load row (0..127)
    const int lc = (t & 1) * 4;     // A-load col offset within 8
    const int bk = t >> 5;          // B-load k row (0..7)
    const int bn = (t & 31) * 4;    // B-load col

    int tile = g;
    const float* vb; long vstr; const float* Wb;
    if (tile < 2048) { vb = inputs + (long)tile * 128; vstr = SFD; }
    else             { vb = stat;                      vstr = DS_; }
    Wb = W + (long)tile * 16384;

    int kk = 0;
    float4 av = *(const float4*)(vb + (long)lm * vstr + kk + lc);
    float4 bv = *(const float4*)(Wb + (kk + bk) * 128 + bn);

    while (true) {
        __syncthreads();   // previous compute done reading smem
        As[lc + 0][lm] = av.x; As[lc + 1][lm] = av.y;
        As[lc + 2][lm] = av.z; As[lc + 3][lm] = av.w;
        *(float4*)(&Bs[bk][bn]) = bv;
        __syncthreads();

        // advance + prefetch next chunk (overlaps with compute below)
        bool more = true;
        int nkk = kk + 8, ntile = tile;
        if (nkk == 128) {
            nkk = 0; ntile = tile + G_;
            if (ntile >= NTILES) more = false;
        }
        if (more) {
            if (ntile != tile) {
                if (ntile < 2048) { vb = inputs + (long)ntile * 128; vstr = SFD; }
                else              { vb = stat;                       vstr = DS_; }
                Wb = W + (long)ntile * 16384;
            }
            av = *(const float4*)(vb + (long)lm * vstr + nkk + lc);
            bv = *(const float4*)(Wb + (nkk + bk) * 128 + bn);
        }

#pragma unroll
        for (int k = 0; k < 8; k++) {
            float4 a0 = *(const float4*)(&As[k][ty * 8]);
            float4 a1 = *(const float4*)(&As[k][ty * 8 + 4]);
            ulonglong2 b0 = *(const ulonglong2*)(&Bs[k][tx * 8]);
            ulonglong2 b1 = *(const ulonglong2*)(&Bs[k][tx * 8 + 4]);
            unsigned long long bp[4] = {b0.x, b0.y, b1.x, b1.y};
            float a[8] = {a0.x, a0.y, a0.z, a0.w, a1.x, a1.y, a1.z, a1.w};
#pragma unroll
            for (int i = 0; i < 8; i++) {
                unsigned long long ap = pack2(a[i], a[i]);
#pragma unroll
                for (int j = 0; j < 4; j++)
                    acc2[i][j] = ffma2(ap, bp[j], acc2[i][j]);
            }
        }

        if (!more) break;
        kk = nkk; tile = ntile;
    }

    float* dst = g_partial + ((long)g * 2 + which) * 16384;
#pragma unroll
    for (int i = 0; i < 8; i++) {
        float4 v0, v1;
        unpack2(acc2[i][0], v0.x, v0.y);
        unpack2(acc2[i][1], v0.z, v0.w);
        unpack2(acc2[i][2], v1.x, v1.y);
        unpack2(acc2[i][3], v1.z, v1.w);
        *(float4*)(dst + (ty * 8 + i) * 128 + tx * 8)     = v0;
        *(float4*)(dst + (ty * 8 + i) * 128 + tx * 8 + 4) = v1;
    }
}

// ---------------------------------------------------------------------------
// Kernel 2: selection head. One block per batch row, 128 threads.
// ---------------------------------------------------------------------------
__global__ __launch_bounds__(128) void k_select(
    const float* __restrict__ cbe,
    const float* __restrict__ cWl,  const float* __restrict__ cbl,
    const float* __restrict__ cWgl, const float* __restrict__ cbgl,
    const float* __restrict__ cWgs, const float* __restrict__ cbgs,
    const float* __restrict__ cgamma, const float* __restrict__ cbeta,
    const float* __restrict__ cbp,
    const float* __restrict__ Ws,   const float* __restrict__ bs)
{
    const int b = blockIdx.x, t = threadIdx.x;
    __shared__ float h[128], h2[128], yv[128];
    __shared__ float red[4];

    float s0 = 0.f, s1 = 0.f;
    const float* p = g_partial + b * 128 + t;
    for (int g = 0; g < G_; ++g) {
        s0 += p[(size_t)(g * 2 + 0) * 16384];
        s1 += p[(size_t)(g * 2 + 1) * 16384];
    }

    float hv = s0 + cbe[t];
    h[t] = hv > 0.f ? hv : expm1f(hv);           // elu
    __syncthreads();

    float a = 0.f;
    for (int k = 0; k < 128; k++) a += h[k] * cWl[k * 128 + t];
    h2[t] = a + cbl[t];
    __syncthreads();

    float gl = cbgl[t], gs = cbgs[t];
    for (int k = 0; k < 128; k++) {
        float hk = h2[k];
        gl += hk * cWgl[k * 128 + t];
        gs += hk * cWgs[k * 128 + t];
    }
    float r = s1 + cbp[t] + gl * (1.f / (1.f + expf(-gs)));

    float sm = r;
    for (int o = 16; o; o >>= 1) sm += __shfl_xor_sync(~0u, sm, o);
    if ((t & 31) == 0) red[t >> 5] = sm;
    __syncthreads();
    float mean = (red[0] + red[1] + red[2] + red[3]) * (1.f / 128.f);
    float d = r - mean;
    float sq = d * d;
    for (int o = 16; o; o >>= 1) sq += __shfl_xor_sync(~0u, sq, o);
    __syncthreads();
    if ((t & 31) == 0) red[t >> 5] = sq;
    __syncthreads();
    float var = (red[0] + red[1] + red[2] + red[3]) * (1.f / 128.f);
    yv[t] = d * rsqrtf(var + 1e-3f) * cgamma[t] + cbeta[t];
    __syncthreads();

    if (t < 32) {
        float l = bs[t];
        for (int k = 0; k < 128; k++) l += yv[k] * Ws[k * 32 + t];
        float mx = l;
        for (int o = 16; o; o >>= 1) mx = fmaxf(mx, __shfl_xor_sync(~0u, mx, o));
        float e = expf(l - mx);
        float ss = e;
        for (int o = 16; o; o >>= 1) ss += __shfl_xor_sync(~0u, ss, o);
        g_wsel[b * 32 + t] = e / ss;
    }
}

// ---------------------------------------------------------------------------
// Kernel 3: per-(batch, feature) GRN. Grid (B, F), 256 threads, 96 KB smem
// -> 2 blocks/SM. FFMA2 inner product. Residual x in registers.
// ---------------------------------------------------------------------------
__device__ __forceinline__ void mmhalf(const float* __restrict__ A,
                                       const float* __restrict__ W,
                                       int rb, int cb, int kbase,
                                       unsigned long long acc2[4][4])
{
#pragma unroll 2
    for (int kk = 0; kk < 64; kk += 4) {
        float4 av[4];
#pragma unroll
        for (int i = 0; i < 4; i++)
            av[i] = *(const float4*)(A + (rb + i) * 128 + kbase + kk);
#pragma unroll
        for (int dk = 0; dk < 4; dk++) {
            ulonglong2 w0 = *(const ulonglong2*)(W + (kk + dk) * 128 + cb);
            ulonglong2 w1 = *(const ulonglong2*)(W + (kk + dk) * 128 + cb + 4);
            unsigned long long bp[4] = {w0.x, w0.y, w1.x, w1.y};
#pragma unroll
            for (int i = 0; i < 4; i++) {
                float a = ((const float*)&av[i])[dk];
                unsigned long long ap = pack2(a, a);
#pragma unroll
                for (int j = 0; j < 4; j++)
                    acc2[i][j] = ffma2(ap, bp[j], acc2[i][j]);
            }
        }
    }
}

// Full [64x128]@[128x128] stage: weight streamed in two 64-row halves.
__device__ __forceinline__ void gemm_stage(const float* __restrict__ A,
                                           const float* __restrict__ Wg,
                                           float* __restrict__ Wsm,
                                           int t, int rb, int cb, float acc[4][8])
{
    unsigned long long acc2[4][4];
#pragma unroll
    for (int i = 0; i < 4; i++)
#pragma unroll
        for (int j = 0; j < 4; j++) acc2[i][j] = 0ull;

#pragma unroll
    for (int h = 0; h < 2; h++) {
        __syncthreads();            // Wsm free to overwrite; A writes visible
        const float* src = Wg + h * 8192;
#pragma unroll
        for (int i = t * 4; i < 8192; i += 1024)
            *(float4*)(Wsm + i) = *(const float4*)(src + i);
        __syncthreads();
        mmhalf(A, Wsm, rb, cb, h * 64, acc2);
    }

#pragma unroll
    for (int i = 0; i < 4; i++) {
        unpack2(acc2[i][0], acc[i][0], acc[i][1]);
        unpack2(acc2[i][1], acc[i][2], acc[i][3]);
        unpack2(acc2[i][2], acc[i][4], acc[i][5]);
        unpack2(acc2[i][3], acc[i][6], acc[i][7]);
    }
}

__global__ __launch_bounds__(256, 2) void k_grn(
    const float* __restrict__ inputs,
    const float* __restrict__ fWe,  const float* __restrict__ fbe,
    const float* __restrict__ fWl,  const float* __restrict__ fbl,
    const float* __restrict__ fWgl, const float* __restrict__ fbgl,
    const float* __restrict__ fWgs, const float* __restrict__ fbgs,
    const float* __restrict__ fgamma, const float* __restrict__ fbeta)
{
    extern __shared__ float smem[];
    float* bufA = smem;            // [64][128]  x -> h2 -> z
    float* bufB = smem + 8192;     // [64][128]  h -> gl
    float* Wsm  = smem + 16384;    // [64][128]  weight half

    const int t  = threadIdx.x;
    const int tx = t & 15, ty = t >> 4;
    const int rb = ty * 4, cb = tx * 8;
    const int b = blockIdx.x, f = blockIdx.y;
    const int r0 = b * 64;
    const int wid = t >> 5, lane = t & 31;

    // load x tile into bufA
#pragma unroll
    for (int i = t * 4; i < 8192; i += 1024) {
        int r = i >> 7, c = i & 127;
        *(float4*)(bufA + i) =
            *(const float4*)(inputs + (size_t)(r0 + r) * 4096 + f * 128 + c);
    }
    __syncthreads();

    // keep residual x patch in registers (this thread's 4x8 output tile)
    float4 xr0[4], xr1[4];
#pragma unroll
    for (int i = 0; i < 4; i++) {
        xr0[i] = *(const float4*)(bufA + (rb + i) * 128 + cb);
        xr1[i] = *(const float4*)(bufA + (rb + i) * 128 + cb + 4);
    }

    float acc[4][8];

    // stage 1: h = elu(x @ We + be)   (bufA -> bufB)
    gemm_stage(bufA, fWe + (size_t)f * 16384, Wsm, t, rb, cb, acc);
    {
        const float* bias = fbe + f * 128;
        float bj[8];
#pragma unroll
        for (int j = 0; j < 8; j++) bj[j] = bias[cb + j];
#pragma unroll
        for (int i = 0; i < 4; i++) {
            float o[8];
#pragma unroll
            for (int j = 0; j < 8; j++) {
                float v = acc[i][j] + bj[j];
                o[j] = v > 0.f ? v : (__expf(v) - 1.f);
            }
            *(float4*)(bufB + (rb + i) * 128 + cb)     = make_float4(o[0], o[1], o[2], o[3]);
            *(float4*)(bufB + (rb + i) * 128 + cb + 4) = make_float4(o[4], o[5], o[6], o[7]);
        }
    }

    // stage 2: h2 = h @ Wl + bl   (bufB -> bufA; x now lives only in regs)
    gemm_stage(bufB, fWl + (size_t)f * 16384, Wsm, t, rb, cb, acc);
    {
        const float* bias = fbl + f * 128;
        float bj[8];
#pragma unroll
        for (int j = 0; j < 8; j++) bj[j] = bias[cb + j];
#pragma unroll
        for (int i = 0; i < 4; i++) {
            *(float4*)(bufA + (rb + i) * 128 + cb) =
                make_float4(acc[i][0] + bj[0], acc[i][1] + bj[1],
                            acc[i][2] + bj[2], acc[i][3] + bj[3]);
            *(float4*)(bufA + (rb + i) * 128 + cb + 4) =
                make_float4(acc[i][4] + bj[4], acc[i][5] + bj[5],
                            acc[i][6] + bj[6], acc[i][7] + bj[7]);
        }
    }

    // stage 3: gl = h2 @ Wgl + bgl   (bufA -> bufB)
    gemm_stage(bufA, fWgl + (size_t)f * 16384, Wsm, t, rb, cb, acc);
    {
        const float* bias = fbgl + f * 128;
        float bj[8];
#pragma unroll
        for (int j = 0; j < 8; j++) bj[j] = bias[cb + j];
#pragma unroll
        for (int i = 0; i < 4; i++) {
            *(float4*)(bufB + (rb + i) * 128 + cb) =
                make_float4(acc[i][0] + bj[0], acc[i][1] + bj[1],
                            acc[i][2] + bj[2], acc[i][3] + bj[3]);
            *(float4*)(bufB + (rb + i) * 128 + cb + 4) =
                make_float4(acc[i][4] + bj[4], acc[i][5] + bj[5],
                            acc[i][6] + bj[6], acc[i][7] + bj[7]);
        }
    }

    // stage 4: gs = h2 @ Wgs + bgs (regs); z = x + gl * sigmoid(gs) -> bufA
    gemm_stage(bufA, fWgs + (size_t)f * 16384, Wsm, t, rb, cb, acc);
    __syncthreads();      // all stage-4 GEMM reads of bufA (h2) complete
    {
        const float* bias = fbgs + f * 128;
        float bj[8];
#pragma unroll
        for (int j = 0; j < 8; j++) bj[j] = bias[cb + j];
#pragma unroll
        for (int i = 0; i < 4; i++) {
            int base = (rb + i) * 128 + cb;
            float4 gl0 = *(const float4*)(bufB + base);
            float4 gl1 = *(const float4*)(bufB + base + 4);
            float s[8];
#pragma unroll
            for (int j = 0; j < 8; j++) {
                float gsv = acc[i][j] + bj[j];
                s[j] = __fdividef(1.f, 1.f + __expf(-gsv));
            }
            float4 z0, z1;
            z0.x = xr0[i].x + gl0.x * s[0]; z0.y = xr0[i].y + gl0.y * s[1];
            z0.z = xr0[i].z + gl0.z * s[2]; z0.w = xr0[i].w + gl0.w * s[3];
            z1.x = xr1[i].x + gl1.x * s[4]; z1.y = xr1[i].y + gl1.y * s[5];
            z1.z = xr1[i].z + gl1.z * s[6]; z1.w = xr1[i].w + gl1.w * s[7];
            *(float4*)(bufA + base)     = z0;
            *(float4*)(bufA + base + 4) = z1;
        }
    }
    __syncthreads();

    // LayerNorm per row, write to per-feature partial buffer (unweighted)
    {
        const float* gam = fgamma + f * 128;
        const float* bet = fbeta + f * 128;
        float* dst = g_part + (size_t)f * 1048576 + (size_t)r0 * 128;
        for (int r = wid; r < 64; r += 8) {
            float z0 = bufA[r * 128 + lane];
            float z1 = bufA[r * 128 + lane + 32];
            float z2 = bufA[r * 128 + lane + 64];
            float z3 = bufA[r * 128 + lane + 96];
            float s = z0 + z1 + z2 + z3;
            for (int o = 16; o; o >>= 1) s += __shfl_xor_sync(~0u, s, o);
            float mean = s * (1.f / 128.f);
            float d0 = z0 - mean, d1 = z1 - mean, d2 = z2 - mean, d3 = z3 - mean;
            float sq = d0 * d0 + d1 * d1 + d2 * d2 + d3 * d3;
            for (int o = 16; o; o >>= 1) sq += __shfl_xor_sync(~0u, sq, o);
            float rstd = rsqrtf(sq * (1.f / 128.f) + 1e-3f);
            dst[r * 128 + lane]      = d0 * rstd * gam[lane]      + bet[lane];
            dst[r * 128 + lane + 32] = d1 * rstd * gam[lane + 32] + bet[lane + 32];
            dst[r * 128 + lane + 64] = d2 * rstd * gam[lane + 64] + bet[lane + 64];
            dst[r * 128 + lane + 96] = d3 * rstd * gam[lane + 96] + bet[lane + 96];
        }
    }
}

// ---------------------------------------------------------------------------
// Kernel 4: deterministic softmax-weighted combine over features.
// ---------------------------------------------------------------------------
__global__ __launch_bounds__(256) void k_combine(float* __restrict__ out)
{
    __shared__ float ws[32];
    const int b = blockIdx.x >> 3;       // 8 blocks per batch row group
    if (threadIdx.x < 32) ws[threadIdx.x] = g_wsel[b * 32 + threadIdx.x];
    __syncthreads();

    const size_t gid = (size_t)blockIdx.x * 256 + threadIdx.x;   // float4 index
    float4 acc = make_float4(0.f, 0.f, 0.f, 0.f);
#pragma unroll 8
    for (int f = 0; f < 32; f++) {
        float4 v = ((const float4*)g_part)[(size_t)f * 262144 + gid];
        float w = ws[f];
        acc.x += w * v.x; acc.y += w * v.y;
        acc.z += w * v.z; acc.w += w * v.w;
    }
    ((float4*)out)[gid] = acc;
}

// ---------------------------------------------------------------------------
extern "C" void kernel_launch(void* const* d_in, const int* in_sizes, int n_in,
                              void* d_out, int out_size)
{
    const float* inputs = (const float*)d_in[0];
    const float* stat   = (const float*)d_in[1];
    const float* cWe    = (const float*)d_in[2];
    const float* cbe    = (const float*)d_in[3];
    const float* cWl    = (const float*)d_in[4];
    const float* cbl    = (const float*)d_in[5];
    const float* cWgl   = (const float*)d_in[6];
    const float* cbgl   = (const float*)d_in[7];
    const float* cWgs   = (const float*)d_in[8];
    const float* cbgs   = (const float*)d_in[9];
    const float* cgamma = (const float*)d_in[10];
    const float* cbeta  = (const float*)d_in[11];
    const float* cWp    = (const float*)d_in[12];
    const float* cbp    = (const float*)d_in[13];
    const float* Ws     = (const float*)d_in[14];
    const float* bs     = (const float*)d_in[15];
    const float* fWe    = (const float*)d_in[16];
    const float* fbe    = (const float*)d_in[17];
    const float* fWl    = (const float*)d_in[18];
    const float* fbl    = (const float*)d_in[19];
    const float* fWgl   = (const float*)d_in[20];
    const float* fbgl   = (const float*)d_in[21];
    const float* fWgs   = (const float*)d_in[22];
    const float* fbgs   = (const float*)d_in[23];
    const float* fgamma = (const float*)d_in[24];
    const float* fbeta  = (const float*)d_in[25];
    float* out = (float*)d_out;

    cudaFuncSetAttribute(k_grn, cudaFuncAttributeMaxDynamicSharedMemorySize, 98304);

    k_biggemm<<<dim3(G_, 2), 256>>>(inputs, stat, cWe, cWp);
    k_select<<<128, 128>>>(cbe, cWl, cbl, cWgl, cbgl, cWgs, cbgs,
                           cgamma, cbeta, cbp, Ws, bs);
    k_grn<<<dim3(B_, F_), 256, 98304>>>(inputs, fWe, fbe, fWl, fbl, fWgl, fbgl,
                                        fWgs, fbgs, fgamma, fbeta);
    k_combine<<<1024, 256>>>(out);
}

// round 12
// speedup vs baseline: 2.5469x; 1.7590x over previous
#include <cuda_runtime.h>
#include <cuda_bf16.h>
#include <math.h>
#include <stdint.h>

#define B_   128
#define S_   64
#define F_   32
#define D_   128
#define U_   128
#define DS_  128
#define SFD  262144          // S*F*D
#define NTILES 2049          // DIN / 128
#define G_   296             // split-K groups for big GEMM

// deterministic split-K scratch: [G_][2][128][128]
__device__ float g_partial[(size_t)G_ * 2 * 128 * 128];
__device__ float g_wsel[B_ * F_];
// per-feature GRN outputs (unweighted LN results): [F][B*S][U] = 134 MB
__device__ float g_part[(size_t)F_ * B_ * S_ * U_];
// fragment-linear bf16 hi/lo weight images: per f 256KB = 4 stages x (hi32K|lo32K)
__device__ unsigned char g_wimg[(size_t)F_ * 262144];

// ---------------------------------------------------------------------------
// Packed f32x2 helpers (k_biggemm)
// ---------------------------------------------------------------------------
__device__ __forceinline__ unsigned long long pack2(float x, float y) {
    unsigned long long r;
    asm("mov.b64 %0, {%1, %2};" : "=l"(r) : "f"(x), "f"(y));
    return r;
}
__device__ __forceinline__ void unpack2(unsigned long long v, float& x, float& y) {
    asm("mov.b64 {%0, %1}, %2;" : "=f"(x), "=f"(y) : "l"(v));
}
__device__ __forceinline__ unsigned long long ffma2(
    unsigned long long a, unsigned long long b, unsigned long long c) {
    unsigned long long d;
    asm("fma.rn.f32x2 %0, %1, %2, %3;" : "=l"(d) : "l"(a), "l"(b), "l"(c));
    return d;
}

// ---------------------------------------------------------------------------
// mma.sync / ldmatrix / cp.async helpers (sm_80-compatible, OK on compute_103)
// ---------------------------------------------------------------------------
__device__ __forceinline__ uint32_t smem_u32(const void* p) {
    uint32_t a;
    asm("{ .reg .u64 t; cvta.to.shared.u64 t, %1; cvt.u32.u64 %0, t; }"
        : "=r"(a) : "l"(p));
    return a;
}
__device__ __forceinline__ void ldm4(uint32_t r[4], uint32_t addr) {
    asm volatile("ldmatrix.sync.aligned.m8n8.x4.shared.b16 {%0,%1,%2,%3}, [%4];"
        : "=r"(r[0]), "=r"(r[1]), "=r"(r[2]), "=r"(r[3]) : "r"(addr));
}
__device__ __forceinline__ uint32_t lds32(uint32_t a) {
    uint32_t v;
    asm volatile("ld.shared.b32 %0, [%1];" : "=r"(v) : "r"(a));
    return v;
}
__device__ __forceinline__ void mma_bf16(float c[4], const uint32_t a[4],
                                         uint32_t b0, uint32_t b1) {
    asm volatile(
        "mma.sync.aligned.m16n8k16.row.col.f32.bf16.bf16.f32 "
        "{%0,%1,%2,%3}, {%4,%5,%6,%7}, {%8,%9}, {%0,%1,%2,%3};"
        : "+f"(c[0]), "+f"(c[1]), "+f"(c[2]), "+f"(c[3])
        : "r"(a[0]), "r"(a[1]), "r"(a[2]), "r"(a[3]), "r"(b0), "r"(b1));
}
__device__ __forceinline__ void cpa16(uint32_t dst, const void* src) {
    asm volatile("cp.async.cg.shared.global [%0], [%1], 16;"
                 :: "r"(dst), "l"(src));
}
#define CP_COMMIT() asm volatile("cp.async.commit_group;")
#define CP_WAIT(n)  asm volatile("cp.async.wait_group %0;" :: "n"(n))

// smem layout for k_grn_mma (bytes)
#define SMW   0          // 131072: two 64KB weight slots
#define SMA_H 131072     // 17408:  Ah [64][136] u16
#define SMA_L 148480     // 17408:  Al [64][136] u16   (Ah+Al reused as zbuf fp32 [64][132])
#define SMX   165888     // 32768:  x residual fp32 [64][128]
#define SMB   198656     // 3072:   biases (be|bl|bgl|bgs|gamma|beta) 6x128
#define SMTOT 201728

// ---------------------------------------------------------------------------
// Weight prep: fp32 [128(d)][128(u)] per (f,stage) -> bf16 hi/lo images in
// mma.sync B-fragment-linear order. word index within an image:
//   ((kt*16 + ntg)*64 + reg*32 + lane) ; value = {B[k'][n], B[k'+1][n]} packed,
//   k' = kt*16 + (lane&3)*2 + reg*8, n = ntg*8 + lane/4, B[k][n] = W[k][n].
// Per f layout: [s1h|s1l|s2h|s2l|s3h|s3l|s4h|s4l], each 8192 words (32KB).
// ---------------------------------------------------------------------------
__global__ __launch_bounds__(256) void k_wprep2(
    const float* __restrict__ fWe, const float* __restrict__ fWl,
    const float* __restrict__ fWgl, const float* __restrict__ fWgs)
{
    int idx = blockIdx.x * 256 + threadIdx.x;   // 32 * 65536
    int f = idx >> 16;
    int w = idx & 65535;
    int seg = w >> 13;          // 0..7
    int widx = w & 8191;
    int stage = seg >> 1;
    int islo = seg & 1;
    int kt = widx >> 10;
    int r  = widx & 1023;
    int ntg = r >> 6;
    int q = r & 63;
    int reg = q >> 5;
    int lane = q & 31;
    int k0 = kt * 16 + (lane & 3) * 2 + reg * 8;
    int n  = ntg * 8 + (lane >> 2);
    const float* src = stage == 0 ? fWe : stage == 1 ? fWl
                     : stage == 2 ? fWgl : fWgs;
    float v0 = src[f * 16384 + k0 * 128 + n];
    float v1 = src[f * 16384 + (k0 + 1) * 128 + n];
    uint32_t word;
    if (!islo) {
        unsigned short h0 = __bfloat16_as_ushort(__float2bfloat16(v0));
        unsigned short h1 = __bfloat16_as_ushort(__float2bfloat16(v1));
        word = (uint32_t)h0 | ((uint32_t)h1 << 16);
    } else {
        __nv_bfloat16 h0 = __float2bfloat16(v0);
        __nv_bfloat16 h1 = __float2bfloat16(v1);
        unsigned short l0 = __bfloat16_as_ushort(__float2bfloat16(v0 - __bfloat162float(h0)));
        unsigned short l1 = __bfloat16_as_ushort(__float2bfloat16(v1 - __bfloat162float(h1)));
        word = (uint32_t)l0 | ((uint32_t)l1 << 16);
    }
    ((uint32_t*)(g_wimg + (size_t)f * 262144))[seg * 8192 + widx] = word;
}

// ---------------------------------------------------------------------------
// Kernel 1: big split-K GEMM (unchanged, fp32+FFMA2)
// ---------------------------------------------------------------------------
__global__ __launch_bounds__(256, 2) void k_biggemm(
    const float* __restrict__ inputs, const float* __restrict__ stat,
    const float* __restrict__ cWe, const float* __restrict__ cWp)
{
    const int g = blockIdx.x, which = blockIdx.y;
    const float* __restrict__ W = which ? cWp : cWe;

    __shared__ __align__(16) float As[8][128];
    __shared__ __align__(16) float Bs[8][128];

    unsigned long long acc2[8][4];
#pragma unroll
    for (int i = 0; i < 8; i++)
#pragma unroll
        for (int j = 0; j < 4; j++) acc2[i][j] = 0ull;

    const int t  = threadIdx.x;
    const int tx = t & 15, ty = t >> 4;
    const int lm = t >> 1;
    const int lc = (t & 1) * 4;
    const int bk = t >> 5;
    const int bn = (t & 31) * 4;

    int tile = g;
    const float* vb; long vstr; const float* Wb;
    if (tile < 2048) { vb = inputs + (long)tile * 128; vstr = SFD; }
    else             { vb = stat;                      vstr = DS_; }
    Wb = W + (long)tile * 16384;

    int kk = 0;
    float4 av = *(const float4*)(vb + (long)lm * vstr + kk + lc);
    float4 bv = *(const float4*)(Wb + (kk + bk) * 128 + bn);

    while (true) {
        __syncthreads();
        As[lc + 0][lm] = av.x; As[lc + 1][lm] = av.y;
        As[lc + 2][lm] = av.z; As[lc + 3][lm] = av.w;
        *(float4*)(&Bs[bk][bn]) = bv;
        __syncthreads();

        bool more = true;
        int nkk = kk + 8, ntile = tile;
        if (nkk == 128) {
            nkk = 0; ntile = tile + G_;
            if (ntile >= NTILES) more = false;
        }
        if (more) {
            if (ntile != tile) {
                if (ntile < 2048) { vb = inputs + (long)ntile * 128; vstr = SFD; }
                else              { vb = stat;                       vstr = DS_; }
                Wb = W + (long)ntile * 16384;
            }
            av = *(const float4*)(vb + (long)lm * vstr + nkk + lc);
            bv = *(const float4*)(Wb + (nkk + bk) * 128 + bn);
        }

#pragma unroll
        for (int k = 0; k < 8; k++) {
            float4 a0 = *(const float4*)(&As[k][ty * 8]);
            float4 a1 = *(const float4*)(&As[k][ty * 8 + 4]);
            ulonglong2 b0 = *(const ulonglong2*)(&Bs[k][tx * 8]);
            ulonglong2 b1 = *(const ulonglong2*)(&Bs[k][tx * 8 + 4]);
            unsigned long long bp[4] = {b0.x, b0.y, b1.x, b1.y};
            float a[8] = {a0.x, a0.y, a0.z, a0.w, a1.x, a1.y, a1.z, a1.w};
#pragma unroll
            for (int i = 0; i < 8; i++) {
                unsigned long long ap = pack2(a[i], a[i]);
#pragma unroll
                for (int j = 0; j < 4; j++)
                    acc2[i][j] = ffma2(ap, bp[j], acc2[i][j]);
            }
        }

        if (!more) break;
        kk = nkk; tile = ntile;
    }

    float* dst = g_partial + ((long)g * 2 + which) * 16384;
#pragma unroll
    for (int i = 0; i < 8; i++) {
        float4 v0, v1;
        unpack2(acc2[i][0], v0.x, v0.y);
        unpack2(acc2[i][1], v0.z, v0.w);
        unpack2(acc2[i][2], v1.x, v1.y);
        unpack2(acc2[i][3], v1.z, v1.w);
        *(float4*)(dst + (ty * 8 + i) * 128 + tx * 8)     = v0;
        *(float4*)(dst + (ty * 8 + i) * 128 + tx * 8 + 4) = v1;
    }
}

// ---------------------------------------------------------------------------
// Kernel 2: selection head (unchanged)
// ---------------------------------------------------------------------------
__global__ __launch_bounds__(128) void k_select(
    const float* __restrict__ cbe,
    const float* __restrict__ cWl,  const float* __restrict__ cbl,
    const float* __restrict__ cWgl, const float* __restrict__ cbgl,
    const float* __restrict__ cWgs, const float* __restrict__ cbgs,
    const float* __restrict__ cgamma, const float* __restrict__ cbeta,
    const float* __restrict__ cbp,
    const float* __restrict__ Ws,   const float* __restrict__ bs)
{
    const int b = blockIdx.x, t = threadIdx.x;
    __shared__ float h[128], h2[128], yv[128];
    __shared__ float red[4];

    float s0 = 0.f, s1 = 0.f;
    const float* p = g_partial + b * 128 + t;
    for (int g = 0; g < G_; ++g) {
        s0 += p[(size_t)(g * 2 + 0) * 16384];
        s1 += p[(size_t)(g * 2 + 1) * 16384];
    }

    float hv = s0 + cbe[t];
    h[t] = hv > 0.f ? hv : expm1f(hv);
    __syncthreads();

    float a = 0.f;
    for (int k = 0; k < 128; k++) a += h[k] * cWl[k * 128 + t];
    h2[t] = a + cbl[t];
    __syncthreads();

    float gl = cbgl[t], gs = cbgs[t];
    for (int k = 0; k < 128; k++) {
        float hk = h2[k];
        gl += hk * cWgl[k * 128 + t];
        gs += hk * cWgs[k * 128 + t];
    }
    float r = s1 + cbp[t] + gl * (1.f / (1.f + expf(-gs)));

    float sm = r;
    for (int o = 16; o; o >>= 1) sm += __shfl_xor_sync(~0u, sm, o);
    if ((t & 31) == 0) red[t >> 5] = sm;
    __syncthreads();
    float mean = (red[0] + red[1] + red[2] + red[3]) * (1.f / 128.f);
    float d = r - mean;
    float sq = d * d;
    for (int o = 16; o; o >>= 1) sq += __shfl_xor_sync(~0u, sq, o);
    __syncthreads();
    if ((t & 31) == 0) red[t >> 5] = sq;
    __syncthreads();
    float var = (red[0] + red[1] + red[2] + red[3]) * (1.f / 128.f);
    yv[t] = d * rsqrtf(var + 1e-3f) * cgamma[t] + cbeta[t];
    __syncthreads();

    if (t < 32) {
        float l = bs[t];
        for (int k = 0; k < 128; k++) l += yv[k] * Ws[k * 32 + t];
        float mx = l;
        for (int o = 16; o; o >>= 1) mx = fmaxf(mx, __shfl_xor_sync(~0u, mx, o));
        float e = expf(l - mx);
        float ss = e;
        for (int o = 16; o; o >>= 1) ss += __shfl_xor_sync(~0u, ss, o);
        g_wsel[b * 32 + t] = e / ss;
    }
}

// ---------------------------------------------------------------------------
// Kernel 3: per-(batch, feature) GRN on mma.sync bf16 (3-pass hi/lo split).
// 512 threads = 16 warps: warp (wm, wn) computes m16 x n32 per stage.
// A (activations) in smem bf16 hi/lo [64][136]; B from fragment-linear images.
// ---------------------------------------------------------------------------
__device__ __forceinline__ void cp64k(uint32_t dst, const unsigned char* src, int t) {
#pragma unroll
    for (int i = 0; i < 8; i++) {
        int o = (t + i * 512) * 16;
        cpa16(dst + o, src + o);
    }
}

__device__ __forceinline__ void run_stage(
    uint32_t aH, uint32_t aL, uint32_t wslot,
    int m0, int wn, int lane, float C[4][4])
{
#pragma unroll
    for (int nt = 0; nt < 4; nt++)
#pragma unroll
        for (int e = 0; e < 4; e++) C[nt][e] = 0.f;

#pragma unroll
    for (int kt = 0; kt < 8; kt++) {
        uint32_t aoff = ((uint32_t)(m0 + (lane & 15)) * 136
                         + (uint32_t)kt * 16 + ((lane >> 4) << 3)) * 2;
        uint32_t ah[4], al[4];
        ldm4(ah, aH + aoff);
        ldm4(al, aL + aoff);
#pragma unroll
        for (int nt = 0; nt < 4; nt++) {
            int ntg = wn * 4 + nt;
            uint32_t b = wslot + (uint32_t)((kt * 16 + ntg) * 64 + lane) * 4;
            uint32_t bh0 = lds32(b), bh1 = lds32(b + 128);
            uint32_t bl0 = lds32(b + 32768), bl1 = lds32(b + 32768 + 128);
            mma_bf16(C[nt], ah, bh0, bh1);
            mma_bf16(C[nt], al, bh0, bh1);
            mma_bf16(C[nt], ah, bl0, bl1);
        }
    }
}

// write activation (optionally elu) back to Ah/Al as bf16 hi/lo
__device__ __forceinline__ void write_act(
    float C[4][4], const float* sb, int boff, bool do_elu,
    unsigned char* smem, int m0, int wn, int lane)
{
    int r0 = m0 + (lane >> 2);
    int nc0 = wn * 32 + ((lane & 3) << 1);
#pragma unroll
    for (int nt = 0; nt < 4; nt++) {
        int n = nc0 + nt * 8;
        float b0 = sb[boff + n], b1 = sb[boff + n + 1];
#pragma unroll
        for (int half = 0; half < 2; half++) {
            int r = r0 + half * 8;
            float v0 = C[nt][half * 2 + 0] + b0;
            float v1 = C[nt][half * 2 + 1] + b1;
            if (do_elu) {
                v0 = v0 > 0.f ? v0 : (__expf(v0) - 1.f);
                v1 = v1 > 0.f ? v1 : (__expf(v1) - 1.f);
            }
            __nv_bfloat16 h0 = __float2bfloat16(v0);
            __nv_bfloat16 h1 = __float2bfloat16(v1);
            unsigned short l0 = __bfloat16_as_ushort(__float2bfloat16(v0 - __bfloat162float(h0)));
            unsigned short l1 = __bfloat16_as_ushort(__float2bfloat16(v1 - __bfloat162float(h1)));
            uint32_t hw = (uint32_t)__bfloat16_as_ushort(h0)
                        | ((uint32_t)__bfloat16_as_ushort(h1) << 16);
            uint32_t lw = (uint32_t)l0 | ((uint32_t)l1 << 16);
            uint32_t off = ((uint32_t)r * 136 + (uint32_t)n) * 2;
            *(uint32_t*)(smem + SMA_H + off) = hw;
            *(uint32_t*)(smem + SMA_L + off) = lw;
        }
    }
}

__global__ __launch_bounds__(512, 1) void k_grn_mma(
    const float* __restrict__ inputs,
    const float* __restrict__ fbe,  const float* __restrict__ fbl,
    const float* __restrict__ fbgl, const float* __restrict__ fbgs,
    const float* __restrict__ fgamma, const float* __restrict__ fbeta)
{
    extern __shared__ __align__(16) unsigned char smem[];
    const uint32_t sb32 = smem_u32(smem);
    float* sb   = (float*)(smem + SMB);
    float* xres = (float*)(smem + SMX);
    float* zbuf = (float*)(smem + SMA_H);   // reused after stage4

    const int t = threadIdx.x;
    const int warp = t >> 5, lane = t & 31;
    const int wm = warp >> 2, wn = warp & 3;
    const int m0 = wm * 16;
    const int p = blockIdx.x, f = blockIdx.y;     // batch, feature
    const unsigned char* img = g_wimg + (size_t)f * 262144;

    // prefetch stage1 + stage2 weight images
    cp64k(sb32 + SMW,         img,         t); CP_COMMIT();
    cp64k(sb32 + SMW + 65536, img + 65536, t); CP_COMMIT();

    // biases
    for (int i = t; i < 768; i += 512) {
        int a = i >> 7, j = i & 127;
        const float* src = a == 0 ? fbe : a == 1 ? fbl : a == 2 ? fbgl
                         : a == 3 ? fbgs : a == 4 ? fgamma : fbeta;
        sb[i] = src[f * 128 + j];
    }

    // prologue: x -> xres (fp32) + Ah/Al (bf16 split). thread: row t>>3, cols (t&7)*16..+15
    {
        int row = t >> 3, c0 = (t & 7) * 16;
        const float* src = inputs + (size_t)(p * 64 + row) * 4096 + f * 128 + c0;
#pragma unroll
        for (int j = 0; j < 4; j++) {
            float4 v = *(const float4*)(src + j * 4);
            *(float4*)(xres + row * 128 + c0 + j * 4) = v;
            float vv[4] = {v.x, v.y, v.z, v.w};
#pragma unroll
            for (int e = 0; e < 4; e += 2) {
                float v0 = vv[e], v1 = vv[e + 1];
                __nv_bfloat16 h0 = __float2bfloat16(v0);
                __nv_bfloat16 h1 = __float2bfloat16(v1);
                unsigned short l0 = __bfloat16_as_ushort(__float2bfloat16(v0 - __bfloat162float(h0)));
                unsigned short l1 = __bfloat16_as_ushort(__float2bfloat16(v1 - __bfloat162float(h1)));
                uint32_t hw = (uint32_t)__bfloat16_as_ushort(h0)
                            | ((uint32_t)__bfloat16_as_ushort(h1) << 16);
                uint32_t lw = (uint32_t)l0 | ((uint32_t)l1 << 16);
                uint32_t off = ((uint32_t)row * 136 + (uint32_t)(c0 + j * 4 + e)) * 2;
                *(uint32_t*)(smem + SMA_H + off) = hw;
                *(uint32_t*)(smem + SMA_L + off) = lw;
            }
        }
    }

    float C[4][4];
    const uint32_t aH = sb32 + SMA_H, aL = sb32 + SMA_L;
    const uint32_t slot0 = sb32 + SMW, slot1 = sb32 + SMW + 65536;

    CP_WAIT(1);                 // stage1 weights arrived
    __syncthreads();

    // ---- stage 1: h = elu(x @ W1 + be) ----
    run_stage(aH, aL, slot0, m0, wn, lane, C);
    __syncthreads();            // all warps done reading x + slot0
    write_act(C, sb, 0, true, smem, m0, wn, lane);
    cp64k(slot0, img + 131072, t); CP_COMMIT();   // stage3 -> slot0
    CP_WAIT(1);                 // stage2 arrived
    __syncthreads();

    // ---- stage 2: h2 = h @ W2 + bl ----
    run_stage(aH, aL, slot1, m0, wn, lane, C);
    __syncthreads();
    write_act(C, sb, 128, false, smem, m0, wn, lane);
    cp64k(slot1, img + 196608, t); CP_COMMIT();   // stage4 -> slot1
    CP_WAIT(1);                 // stage3 arrived
    __syncthreads();

    // ---- stage 3: gl_raw = h2 @ W3 (keep in regs) ----
    float Cgl[4][4];
    run_stage(aH, aL, slot0, m0, wn, lane, Cgl);
    CP_WAIT(0);                 // stage4 arrived
    __syncthreads();

    // ---- stage 4: gs_raw = h2 @ W4 ----
    run_stage(aH, aL, slot1, m0, wn, lane, C);
    __syncthreads();            // all warps done reading Ah/Al before zbuf overwrite

    // z = x + (gl+bgl) * sigmoid(gs+bgs)  -> zbuf fp32 [64][132]
    {
        int r0 = m0 + (lane >> 2);
        int nc0 = wn * 32 + ((lane & 3) << 1);
#pragma unroll
        for (int nt = 0; nt < 4; nt++) {
            int n = nc0 + nt * 8;
            float bgl0 = sb[256 + n], bgl1 = sb[256 + n + 1];
            float bgs0 = sb[384 + n], bgs1 = sb[384 + n + 1];
#pragma unroll
            for (int half = 0; half < 2; half++) {
                int r = r0 + half * 8;
                float gl0 = Cgl[nt][half * 2 + 0] + bgl0;
                float gl1 = Cgl[nt][half * 2 + 1] + bgl1;
                float gs0 = C[nt][half * 2 + 0] + bgs0;
                float gs1 = C[nt][half * 2 + 1] + bgs1;
                float s0 = __fdividef(1.f, 1.f + __expf(-gs0));
                float s1 = __fdividef(1.f, 1.f + __expf(-gs1));
                float2 xv = *(const float2*)(xres + r * 128 + n);
                float2 z;
                z.x = xv.x + gl0 * s0;
                z.y = xv.y + gl1 * s1;
                *(float2*)(zbuf + r * 132 + n) = z;
            }
        }
    }
    __syncthreads();

    // LayerNorm per row (8 threads/row), write to g_part
    {
        int row = t >> 3, sub = t & 7;
        const float* zr = zbuf + row * 132 + sub * 16;
        float4 z4[4];
        float sum = 0.f, sq = 0.f;
#pragma unroll
        for (int j = 0; j < 4; j++) {
            z4[j] = *(const float4*)(zr + j * 4);
            sum += z4[j].x + z4[j].y + z4[j].z + z4[j].w;
            sq  += z4[j].x * z4[j].x + z4[j].y * z4[j].y
                 + z4[j].z * z4[j].z + z4[j].w * z4[j].w;
        }
#pragma unroll
        for (int o = 1; o < 8; o <<= 1) {
            sum += __shfl_xor_sync(~0u, sum, o);
            sq  += __shfl_xor_sync(~0u, sq, o);
        }
        float mean = sum * (1.f / 128.f);
        float var  = sq * (1.f / 128.f) - mean * mean;
        float rstd = rsqrtf(var + 1e-3f);
        float* dst = g_part + (size_t)f * 1048576
                   + (size_t)(p * 64 + row) * 128 + sub * 16;
#pragma unroll
        for (int j = 0; j < 4; j++) {
            int c = sub * 16 + j * 4;
            float4 o;
            o.x = (z4[j].x - mean) * rstd * sb[512 + c + 0] + sb[640 + c + 0];
            o.y = (z4[j].y - mean) * rstd * sb[512 + c + 1] + sb[640 + c + 1];
            o.z = (z4[j].z - mean) * rstd * sb[512 + c + 2] + sb[640 + c + 2];
            o.w = (z4[j].w - mean) * rstd * sb[512 + c + 3] + sb[640 + c + 3];
            *(float4*)(dst + j * 4) = o;
        }
    }
}

// ---------------------------------------------------------------------------
// Kernel 4: deterministic softmax-weighted combine over features (unchanged).
// ---------------------------------------------------------------------------
__global__ __launch_bounds__(256) void k_combine(float* __restrict__ out)
{
    __shared__ float ws[32];
    const int b = blockIdx.x >> 3;
    if (threadIdx.x < 32) ws[threadIdx.x] = g_wsel[b * 32 + threadIdx.x];
    __syncthreads();

    const size_t gid = (size_t)blockIdx.x * 256 + threadIdx.x;
    float4 acc = make_float4(0.f, 0.f, 0.f, 0.f);
#pragma unroll 8
    for (int f = 0; f < 32; f++) {
        float4 v = ((const float4*)g_part)[(size_t)f * 262144 + gid];
        float w = ws[f];
        acc.x += w * v.x; acc.y += w * v.y;
        acc.z += w * v.z; acc.w += w * v.w;
    }
    ((float4*)out)[gid] = acc;
}

// ---------------------------------------------------------------------------
extern "C" void kernel_launch(void* const* d_in, const int* in_sizes, int n_in,
                              void* d_out, int out_size)
{
    const float* inputs = (const float*)d_in[0];
    const float* stat   = (const float*)d_in[1];
    const float* cWe    = (const float*)d_in[2];
    const float* cbe    = (const float*)d_in[3];
    const float* cWl    = (const float*)d_in[4];
    const float* cbl    = (const float*)d_in[5];
    const float* cWgl   = (const float*)d_in[6];
    const float* cbgl   = (const float*)d_in[7];
    const float* cWgs   = (const float*)d_in[8];
    const float* cbgs   = (const float*)d_in[9];
    const float* cgamma = (const float*)d_in[10];
    const float* cbeta  = (const float*)d_in[11];
    const float* cWp    = (const float*)d_in[12];
    const float* cbp    = (const float*)d_in[13];
    const float* Ws     = (const float*)d_in[14];
    const float* bs     = (const float*)d_in[15];
    const float* fWe    = (const float*)d_in[16];
    const float* fbe    = (const float*)d_in[17];
    const float* fWl    = (const float*)d_in[18];
    const float* fbl    = (const float*)d_in[19];
    const float* fWgl   = (const float*)d_in[20];
    const float* fbgl   = (const float*)d_in[21];
    const float* fWgs   = (const float*)d_in[22];
    const float* fbgs   = (const float*)d_in[23];
    const float* fgamma = (const float*)d_in[24];
    const float* fbeta  = (const float*)d_in[25];
    float* out = (float*)d_out;

    cudaFuncSetAttribute(k_grn_mma, cudaFuncAttributeMaxDynamicSharedMemorySize, SMTOT);

    k_wprep2<<<8192, 256>>>(fWe, fWl, fWgl, fWgs);
    k_biggemm<<<dim3(G_, 2), 256>>>(inputs, stat, cWe, cWp);
    k_select<<<128, 128>>>(cbe, cWl, cbl, cWgl, cbgl, cWgs, cbgs,
                           cgamma, cbeta, cbp, Ws, bs);
    k_grn_mma<<<dim3(B_, F_), 512, SMTOT>>>(inputs, fbe, fbl, fbgl, fbgs,
                                            fgamma, fbeta);
    k_combine<<<1024, 256>>>(out);
}

// round 13
// speedup vs baseline: 3.1126x; 1.2221x over previous
#include <cuda_runtime.h>
#include <cuda_bf16.h>
#include <math.h>
#include <stdint.h>

#define B_   128
#define S_   64
#define F_   32
#define D_   128
#define U_   128
#define DS_  128
#define SFD  262144          // S*F*D
#define NTILES 2049          // DIN / 128
#define G_   296             // split-K groups for big GEMM

// deterministic split-K scratch: [G_][2][128][128]
__device__ float g_partial[(size_t)G_ * 2 * 128 * 128];
__device__ float g_wsel[B_ * F_];
// per-feature GRN outputs (unweighted LN results): [F][B*S][U] = 134 MB
__device__ float g_part[(size_t)F_ * B_ * S_ * U_];
// fragment-linear bf16 hi/lo weight images: per f 256KB = 4 stages x (hi32K|lo32K)
__device__ unsigned char g_wimg[(size_t)F_ * 262144];

// ---------------------------------------------------------------------------
// mma.sync / ldmatrix / cp.async helpers (sm_80-compatible, OK on compute_103)
// ---------------------------------------------------------------------------
__device__ __forceinline__ uint32_t smem_u32(const void* p) {
    uint32_t a;
    asm("{ .reg .u64 t; cvta.to.shared.u64 t, %1; cvt.u32.u64 %0, t; }"
        : "=r"(a) : "l"(p));
    return a;
}
__device__ __forceinline__ void ldm4(uint32_t r[4], uint32_t addr) {
    asm volatile("ldmatrix.sync.aligned.m8n8.x4.shared.b16 {%0,%1,%2,%3}, [%4];"
        : "=r"(r[0]), "=r"(r[1]), "=r"(r[2]), "=r"(r[3]) : "r"(addr));
}
__device__ __forceinline__ void ldm4t(uint32_t r[4], uint32_t addr) {
    asm volatile("ldmatrix.sync.aligned.m8n8.x4.trans.shared.b16 {%0,%1,%2,%3}, [%4];"
        : "=r"(r[0]), "=r"(r[1]), "=r"(r[2]), "=r"(r[3]) : "r"(addr));
}
__device__ __forceinline__ uint32_t lds32(uint32_t a) {
    uint32_t v;
    asm volatile("ld.shared.b32 %0, [%1];" : "=r"(v) : "r"(a));
    return v;
}
__device__ __forceinline__ void mma_bf16(float c[4], const uint32_t a[4],
                                         uint32_t b0, uint32_t b1) {
    asm volatile(
        "mma.sync.aligned.m16n8k16.row.col.f32.bf16.bf16.f32 "
        "{%0,%1,%2,%3}, {%4,%5,%6,%7}, {%8,%9}, {%0,%1,%2,%3};"
        : "+f"(c[0]), "+f"(c[1]), "+f"(c[2]), "+f"(c[3])
        : "r"(a[0]), "r"(a[1]), "r"(a[2]), "r"(a[3]), "r"(b0), "r"(b1));
}
__device__ __forceinline__ void cpa16(uint32_t dst, const void* src) {
    asm volatile("cp.async.cg.shared.global [%0], [%1], 16;"
                 :: "r"(dst), "l"(src));
}
#define CP_COMMIT() asm volatile("cp.async.commit_group;")
#define CP_WAIT(n)  asm volatile("cp.async.wait_group %0;" :: "n"(n))

// split fp32 pair -> packed bf16 hi word + lo word
__device__ __forceinline__ void split2(float v0, float v1,
                                       uint32_t& hw, uint32_t& lw) {
    __nv_bfloat16 h0 = __float2bfloat16(v0);
    __nv_bfloat16 h1 = __float2bfloat16(v1);
    unsigned short l0 = __bfloat16_as_ushort(__float2bfloat16(v0 - __bfloat162float(h0)));
    unsigned short l1 = __bfloat16_as_ushort(__float2bfloat16(v1 - __bfloat162float(h1)));
    hw = (uint32_t)__bfloat16_as_ushort(h0) | ((uint32_t)__bfloat16_as_ushort(h1) << 16);
    lw = (uint32_t)l0 | ((uint32_t)l1 << 16);
}

// ---------------------------------------------------------------------------
// Kernel 1: big split-K GEMM on mma.sync bf16 (3-pass hi/lo split).
// Grid (G_, which, nhalf). Block: 256 thr = 8 warps (m32 x n32).
// Per 128-k tile: A[128x128] fp32 + W[128x64] fp32 -> hi/lo bf16 smem -> mma.
// ---------------------------------------------------------------------------
#define BG_AH 0
#define BG_AL 34816
#define BG_WH 69632
#define BG_WL 88064
#define BG_TOT 106496

__global__ __launch_bounds__(256, 2) void k_biggemm_mma(
    const float* __restrict__ inputs, const float* __restrict__ stat,
    const float* __restrict__ cWe, const float* __restrict__ cWp)
{
    extern __shared__ __align__(16) unsigned char smem[];
    const uint32_t sb32 = smem_u32(smem);
    const int g = blockIdx.x, which = blockIdx.y, nhalf = blockIdx.z;
    const float* __restrict__ W = which ? cWp : cWe;
    const int nbase = nhalf * 64;

    const int t = threadIdx.x;
    const int warp = t >> 5, lane = t & 31;
    const int wm = warp >> 1, wn = warp & 1;
    const int m0 = wm * 32;

    float C[2][4][4];
#pragma unroll
    for (int mt = 0; mt < 2; mt++)
#pragma unroll
        for (int n8 = 0; n8 < 4; n8++)
#pragma unroll
            for (int e = 0; e < 4; e++) C[mt][n8][e] = 0.f;

    const uint32_t aH = sb32 + BG_AH, aL = sb32 + BG_AL;
    const uint32_t wH = sb32 + BG_WH, wL = sb32 + BG_WL;

    for (int tile = g; tile < NTILES; tile += G_) {
        const float* vb; long vstr;
        if (tile < 2048) { vb = inputs + (long)tile * 128; vstr = SFD; }
        else             { vb = stat;                      vstr = DS_; }
        const float* Wg = W + (long)tile * 16384 + nbase;

        __syncthreads();   // previous mma done reading smem

        // A: 4096 float4, 16 per thread; one warp iteration = one 128-col row
#pragma unroll
        for (int i = 0; i < 16; i++) {
            int idx4 = t + i * 256;
            int row = idx4 >> 5;
            int c4 = (idx4 & 31) * 4;
            float4 v = *(const float4*)(vb + (long)row * vstr + c4);
            uint32_t hw0, lw0, hw1, lw1;
            split2(v.x, v.y, hw0, lw0);
            split2(v.z, v.w, hw1, lw1);
            uint32_t off = ((uint32_t)row * 136 + (uint32_t)c4) * 2;
            *(uint32_t*)(smem + BG_AH + off)     = hw0;
            *(uint32_t*)(smem + BG_AH + off + 4) = hw1;
            *(uint32_t*)(smem + BG_AL + off)     = lw0;
            *(uint32_t*)(smem + BG_AL + off + 4) = lw1;
        }
        // W: 2048 float4, 8 per thread (64-col half rows)
#pragma unroll
        for (int i = 0; i < 8; i++) {
            int idx4 = t + i * 256;
            int kr = idx4 >> 4;
            int c4 = (idx4 & 15) * 4;
            float4 v = *(const float4*)(Wg + (long)kr * 128 + c4);
            uint32_t hw0, lw0, hw1, lw1;
            split2(v.x, v.y, hw0, lw0);
            split2(v.z, v.w, hw1, lw1);
            uint32_t off = ((uint32_t)kr * 72 + (uint32_t)c4) * 2;
            *(uint32_t*)(smem + BG_WH + off)     = hw0;
            *(uint32_t*)(smem + BG_WH + off + 4) = hw1;
            *(uint32_t*)(smem + BG_WL + off)     = lw0;
            *(uint32_t*)(smem + BG_WL + off + 4) = lw1;
        }
        __syncthreads();

#pragma unroll
        for (int kt = 0; kt < 8; kt++) {
            uint32_t ah[2][4], al[2][4];
#pragma unroll
            for (int mt = 0; mt < 2; mt++) {
                uint32_t aoff = ((uint32_t)(m0 + mt * 16 + (lane & 15)) * 136
                                 + (uint32_t)kt * 16 + ((lane >> 4) << 3)) * 2;
                ldm4(ah[mt], aH + aoff);
                ldm4(al[mt], aL + aoff);
            }
            uint32_t bh[2][4], bl[2][4];
#pragma unroll
            for (int nt = 0; nt < 2; nt++) {
                uint32_t brow = (uint32_t)kt * 16 + ((lane >> 3) & 1) * 8 + (lane & 7);
                uint32_t bcol = (uint32_t)wn * 32 + nt * 16 + ((lane >> 4) << 3);
                uint32_t boff = (brow * 72 + bcol) * 2;
                ldm4t(bh[nt], wH + boff);
                ldm4t(bl[nt], wL + boff);
            }
#pragma unroll
            for (int mt = 0; mt < 2; mt++)
#pragma unroll
                for (int n8 = 0; n8 < 4; n8++) {
                    int nt = n8 >> 1, pr = (n8 & 1) * 2;
                    uint32_t b0h = bh[nt][pr], b1h = bh[nt][pr + 1];
                    uint32_t b0l = bl[nt][pr], b1l = bl[nt][pr + 1];
                    mma_bf16(C[mt][n8], ah[mt], b0h, b1h);
                    mma_bf16(C[mt][n8], al[mt], b0h, b1h);
                    mma_bf16(C[mt][n8], ah[mt], b0l, b1l);
                }
        }
    }

    // epilogue: write partials
    float* dst = g_partial + ((long)g * 2 + which) * 16384 + nbase;
#pragma unroll
    for (int mt = 0; mt < 2; mt++)
#pragma unroll
        for (int n8 = 0; n8 < 4; n8++) {
            int row = m0 + mt * 16 + (lane >> 2);
            int col = wn * 32 + n8 * 8 + (lane & 3) * 2;
            float2 v0 = make_float2(C[mt][n8][0], C[mt][n8][1]);
            float2 v1 = make_float2(C[mt][n8][2], C[mt][n8][3]);
            *(float2*)(dst + (long)row * 128 + col)       = v0;
            *(float2*)(dst + (long)(row + 8) * 128 + col) = v1;
        }
}

// ---------------------------------------------------------------------------
// Weight prep for k_grn_mma (unchanged from R12)
// ---------------------------------------------------------------------------
__global__ __launch_bounds__(256) void k_wprep2(
    const float* __restrict__ fWe, const float* __restrict__ fWl,
    const float* __restrict__ fWgl, const float* __restrict__ fWgs)
{
    int idx = blockIdx.x * 256 + threadIdx.x;   // 32 * 65536
    int f = idx >> 16;
    int w = idx & 65535;
    int seg = w >> 13;          // 0..7
    int widx = w & 8191;
    int stage = seg >> 1;
    int islo = seg & 1;
    int kt = widx >> 10;
    int r  = widx & 1023;
    int ntg = r >> 6;
    int q = r & 63;
    int reg = q >> 5;
    int lane = q & 31;
    int k0 = kt * 16 + (lane & 3) * 2 + reg * 8;
    int n  = ntg * 8 + (lane >> 2);
    const float* src = stage == 0 ? fWe : stage == 1 ? fWl
                     : stage == 2 ? fWgl : fWgs;
    float v0 = src[f * 16384 + k0 * 128 + n];
    float v1 = src[f * 16384 + (k0 + 1) * 128 + n];
    uint32_t word;
    if (!islo) {
        unsigned short h0 = __bfloat16_as_ushort(__float2bfloat16(v0));
        unsigned short h1 = __bfloat16_as_ushort(__float2bfloat16(v1));
        word = (uint32_t)h0 | ((uint32_t)h1 << 16);
    } else {
        __nv_bfloat16 h0 = __float2bfloat16(v0);
        __nv_bfloat16 h1 = __float2bfloat16(v1);
        unsigned short l0 = __bfloat16_as_ushort(__float2bfloat16(v0 - __bfloat162float(h0)));
        unsigned short l1 = __bfloat16_as_ushort(__float2bfloat16(v1 - __bfloat162float(h1)));
        word = (uint32_t)l0 | ((uint32_t)l1 << 16);
    }
    ((uint32_t*)(g_wimg + (size_t)f * 262144))[seg * 8192 + widx] = word;
}

// ---------------------------------------------------------------------------
// Kernel 2: selection head (unchanged)
// ---------------------------------------------------------------------------
__global__ __launch_bounds__(128) void k_select(
    const float* __restrict__ cbe,
    const float* __restrict__ cWl,  const float* __restrict__ cbl,
    const float* __restrict__ cWgl, const float* __restrict__ cbgl,
    const float* __restrict__ cWgs, const float* __restrict__ cbgs,
    const float* __restrict__ cgamma, const float* __restrict__ cbeta,
    const float* __restrict__ cbp,
    const float* __restrict__ Ws,   const float* __restrict__ bs)
{
    const int b = blockIdx.x, t = threadIdx.x;
    __shared__ float h[128], h2[128], yv[128];
    __shared__ float red[4];

    float s0 = 0.f, s1 = 0.f;
    const float* p = g_partial + b * 128 + t;
    for (int g = 0; g < G_; ++g) {
        s0 += p[(size_t)(g * 2 + 0) * 16384];
        s1 += p[(size_t)(g * 2 + 1) * 16384];
    }

    float hv = s0 + cbe[t];
    h[t] = hv > 0.f ? hv : expm1f(hv);
    __syncthreads();

    float a = 0.f;
    for (int k = 0; k < 128; k++) a += h[k] * cWl[k * 128 + t];
    h2[t] = a + cbl[t];
    __syncthreads();

    float gl = cbgl[t], gs = cbgs[t];
    for (int k = 0; k < 128; k++) {
        float hk = h2[k];
        gl += hk * cWgl[k * 128 + t];
        gs += hk * cWgs[k * 128 + t];
    }
    float r = s1 + cbp[t] + gl * (1.f / (1.f + expf(-gs)));

    float sm = r;
    for (int o = 16; o; o >>= 1) sm += __shfl_xor_sync(~0u, sm, o);
    if ((t & 31) == 0) red[t >> 5] = sm;
    __syncthreads();
    float mean = (red[0] + red[1] + red[2] + red[3]) * (1.f / 128.f);
    float d = r - mean;
    float sq = d * d;
    for (int o = 16; o; o >>= 1) sq += __shfl_xor_sync(~0u, sq, o);
    __syncthreads();
    if ((t & 31) == 0) red[t >> 5] = sq;
    __syncthreads();
    float var = (red[0] + red[1] + red[2] + red[3]) * (1.f / 128.f);
    yv[t] = d * rsqrtf(var + 1e-3f) * cgamma[t] + cbeta[t];
    __syncthreads();

    if (t < 32) {
        float l = bs[t];
        for (int k = 0; k < 128; k++) l += yv[k] * Ws[k * 32 + t];
        float mx = l;
        for (int o = 16; o; o >>= 1) mx = fmaxf(mx, __shfl_xor_sync(~0u, mx, o));
        float e = expf(l - mx);
        float ss = e;
        for (int o = 16; o; o >>= 1) ss += __shfl_xor_sync(~0u, ss, o);
        g_wsel[b * 32 + t] = e / ss;
    }
}

// ---------------------------------------------------------------------------
// Kernel 3: per-(batch, feature) GRN on mma.sync bf16 (unchanged from R12)
// ---------------------------------------------------------------------------
#define SMW   0
#define SMA_H 131072
#define SMA_L 148480
#define SMX   165888
#define SMB   198656
#define SMTOT 201728

__device__ __forceinline__ void cp64k(uint32_t dst, const unsigned char* src, int t) {
#pragma unroll
    for (int i = 0; i < 8; i++) {
        int o = (t + i * 512) * 16;
        cpa16(dst + o, src + o);
    }
}

__device__ __forceinline__ void run_stage(
    uint32_t aH, uint32_t aL, uint32_t wslot,
    int m0, int wn, int lane, float C[4][4])
{
#pragma unroll
    for (int nt = 0; nt < 4; nt++)
#pragma unroll
        for (int e = 0; e < 4; e++) C[nt][e] = 0.f;

#pragma unroll
    for (int kt = 0; kt < 8; kt++) {
        uint32_t aoff = ((uint32_t)(m0 + (lane & 15)) * 136
                         + (uint32_t)kt * 16 + ((lane >> 4) << 3)) * 2;
        uint32_t ah[4], al[4];
        ldm4(ah, aH + aoff);
        ldm4(al, aL + aoff);
#pragma unroll
        for (int nt = 0; nt < 4; nt++) {
            int ntg = wn * 4 + nt;
            uint32_t b = wslot + (uint32_t)((kt * 16 + ntg) * 64 + lane) * 4;
            uint32_t bh0 = lds32(b), bh1 = lds32(b + 128);
            uint32_t bl0 = lds32(b + 32768), bl1 = lds32(b + 32768 + 128);
            mma_bf16(C[nt], ah, bh0, bh1);
            mma_bf16(C[nt], al, bh0, bh1);
            mma_bf16(C[nt], ah, bl0, bl1);
        }
    }
}

__device__ __forceinline__ void write_act(
    float C[4][4], const float* sb, int boff, bool do_elu,
    unsigned char* smem, int m0, int wn, int lane)
{
    int r0 = m0 + (lane >> 2);
    int nc0 = wn * 32 + ((lane & 3) << 1);
#pragma unroll
    for (int nt = 0; nt < 4; nt++) {
        int n = nc0 + nt * 8;
        float b0 = sb[boff + n], b1 = sb[boff + n + 1];
#pragma unroll
        for (int half = 0; half < 2; half++) {
            int r = r0 + half * 8;
            float v0 = C[nt][half * 2 + 0] + b0;
            float v1 = C[nt][half * 2 + 1] + b1;
            if (do_elu) {
                v0 = v0 > 0.f ? v0 : (__expf(v0) - 1.f);
                v1 = v1 > 0.f ? v1 : (__expf(v1) - 1.f);
            }
            uint32_t hw, lw;
            split2(v0, v1, hw, lw);
            uint32_t off = ((uint32_t)r * 136 + (uint32_t)n) * 2;
            *(uint32_t*)(smem + SMA_H + off) = hw;
            *(uint32_t*)(smem + SMA_L + off) = lw;
        }
    }
}

__global__ __launch_bounds__(512, 1) void k_grn_mma(
    const float* __restrict__ inputs,
    const float* __restrict__ fbe,  const float* __restrict__ fbl,
    const float* __restrict__ fbgl, const float* __restrict__ fbgs,
    const float* __restrict__ fgamma, const float* __restrict__ fbeta)
{
    extern __shared__ __align__(16) unsigned char smem[];
    const uint32_t sb32 = smem_u32(smem);
    float* sb   = (float*)(smem + SMB);
    float* xres = (float*)(smem + SMX);
    float* zbuf = (float*)(smem + SMA_H);   // reused after stage4

    const int t = threadIdx.x;
    const int warp = t >> 5, lane = t & 31;
    const int wm = warp >> 2, wn = warp & 3;
    const int m0 = wm * 16;
    const int p = blockIdx.x, f = blockIdx.y;
    const unsigned char* img = g_wimg + (size_t)f * 262144;

    cp64k(sb32 + SMW,         img,         t); CP_COMMIT();
    cp64k(sb32 + SMW + 65536, img + 65536, t); CP_COMMIT();

    for (int i = t; i < 768; i += 512) {
        int a = i >> 7, j = i & 127;
        const float* src = a == 0 ? fbe : a == 1 ? fbl : a == 2 ? fbgl
                         : a == 3 ? fbgs : a == 4 ? fgamma : fbeta;
        sb[i] = src[f * 128 + j];
    }

    {
        int row = t >> 3, c0 = (t & 7) * 16;
        const float* src = inputs + (size_t)(p * 64 + row) * 4096 + f * 128 + c0;
#pragma unroll
        for (int j = 0; j < 4; j++) {
            float4 v = *(const float4*)(src + j * 4);
            *(float4*)(xres + row * 128 + c0 + j * 4) = v;
            uint32_t hw0, lw0, hw1, lw1;
            split2(v.x, v.y, hw0, lw0);
            split2(v.z, v.w, hw1, lw1);
            uint32_t off = ((uint32_t)row * 136 + (uint32_t)(c0 + j * 4)) * 2;
            *(uint32_t*)(smem + SMA_H + off)     = hw0;
            *(uint32_t*)(smem + SMA_H + off + 4) = hw1;
            *(uint32_t*)(smem + SMA_L + off)     = lw0;
            *(uint32_t*)(smem + SMA_L + off + 4) = lw1;
        }
    }

    float C[4][4];
    const uint32_t aH = sb32 + SMA_H, aL = sb32 + SMA_L;
    const uint32_t slot0 = sb32 + SMW, slot1 = sb32 + SMW + 65536;

    CP_WAIT(1);
    __syncthreads();

    run_stage(aH, aL, slot0, m0, wn, lane, C);
    __syncthreads();
    write_act(C, sb, 0, true, smem, m0, wn, lane);
    cp64k(slot0, img + 131072, t); CP_COMMIT();
    CP_WAIT(1);
    __syncthreads();

    run_stage(aH, aL, slot1, m0, wn, lane, C);
    __syncthreads();
    write_act(C, sb, 128, false, smem, m0, wn, lane);
    cp64k(slot1, img + 196608, t); CP_COMMIT();
    CP_WAIT(1);
    __syncthreads();

    float Cgl[4][4];
    run_stage(aH, aL, slot0, m0, wn, lane, Cgl);
    CP_WAIT(0);
    __syncthreads();

    run_stage(aH, aL, slot1, m0, wn, lane, C);
    __syncthreads();

    {
        int r0 = m0 + (lane >> 2);
        int nc0 = wn * 32 + ((lane & 3) << 1);
#pragma unroll
        for (int nt = 0; nt < 4; nt++) {
            int n = nc0 + nt * 8;
            float bgl0 = sb[256 + n], bgl1 = sb[256 + n + 1];
            float bgs0 = sb[384 + n], bgs1 = sb[384 + n + 1];
#pragma unroll
            for (int half = 0; half < 2; half++) {
                int r = r0 + half * 8;
                float gl0 = Cgl[nt][half * 2 + 0] + bgl0;
                float gl1 = Cgl[nt][half * 2 + 1] + bgl1;
                float gs0 = C[nt][half * 2 + 0] + bgs0;
                float gs1 = C[nt][half * 2 + 1] + bgs1;
                float s0 = __fdividef(1.f, 1.f + __expf(-gs0));
                float s1 = __fdividef(1.f, 1.f + __expf(-gs1));
                float2 xv = *(const float2*)(xres + r * 128 + n);
                float2 z;
                z.x = xv.x + gl0 * s0;
                z.y = xv.y + gl1 * s1;
                *(float2*)(zbuf + r * 132 + n) = z;
            }
        }
    }
    __syncthreads();

    {
        int row = t >> 3, sub = t & 7;
        const float* zr = zbuf + row * 132 + sub * 16;
        float4 z4[4];
        float sum = 0.f, sq = 0.f;
#pragma unroll
        for (int j = 0; j < 4; j++) {
            z4[j] = *(const float4*)(zr + j * 4);
            sum += z4[j].x + z4[j].y + z4[j].z + z4[j].w;
            sq  += z4[j].x * z4[j].x + z4[j].y * z4[j].y
                 + z4[j].z * z4[j].z + z4[j].w * z4[j].w;
        }
#pragma unroll
        for (int o = 1; o < 8; o <<= 1) {
            sum += __shfl_xor_sync(~0u, sum, o);
            sq  += __shfl_xor_sync(~0u, sq, o);
        }
        float mean = sum * (1.f / 128.f);
        float var  = sq * (1.f / 128.f) - mean * mean;
        float rstd = rsqrtf(var + 1e-3f);
        float* dst = g_part + (size_t)f * 1048576
                   + (size_t)(p * 64 + row) * 128 + sub * 16;
#pragma unroll
        for (int j = 0; j < 4; j++) {
            int c = sub * 16 + j * 4;
            float4 o;
            o.x = (z4[j].x - mean) * rstd * sb[512 + c + 0] + sb[640 + c + 0];
            o.y = (z4[j].y - mean) * rstd * sb[512 + c + 1] + sb[640 + c + 1];
            o.z = (z4[j].z - mean) * rstd * sb[512 + c + 2] + sb[640 + c + 2];
            o.w = (z4[j].w - mean) * rstd * sb[512 + c + 3] + sb[640 + c + 3];
            *(float4*)(dst + j * 4) = o;
        }
    }
}

// ---------------------------------------------------------------------------
// Kernel 4: deterministic softmax-weighted combine over features (unchanged).
// ---------------------------------------------------------------------------
__global__ __launch_bounds__(256) void k_combine(float* __restrict__ out)
{
    __shared__ float ws[32];
    const int b = blockIdx.x >> 3;
    if (threadIdx.x < 32) ws[threadIdx.x] = g_wsel[b * 32 + threadIdx.x];
    __syncthreads();

    const size_t gid = (size_t)blockIdx.x * 256 + threadIdx.x;
    float4 acc = make_float4(0.f, 0.f, 0.f, 0.f);
#pragma unroll 8
    for (int f = 0; f < 32; f++) {
        float4 v = ((const float4*)g_part)[(size_t)f * 262144 + gid];
        float w = ws[f];
        acc.x += w * v.x; acc.y += w * v.y;
        acc.z += w * v.z; acc.w += w * v.w;
    }
    ((float4*)out)[gid] = acc;
}

// ---------------------------------------------------------------------------
extern "C" void kernel_launch(void* const* d_in, const int* in_sizes, int n_in,
                              void* d_out, int out_size)
{
    const float* inputs = (const float*)d_in[0];
    const float* stat   = (const float*)d_in[1];
    const float* cWe    = (const float*)d_in[2];
    const float* cbe    = (const float*)d_in[3];
    const float* cWl    = (const float*)d_in[4];
    const float* cbl    = (const float*)d_in[5];
    const float* cWgl   = (const float*)d_in[6];
    const float* cbgl   = (const float*)d_in[7];
    const float* cWgs   = (const float*)d_in[8];
    const float* cbgs   = (const float*)d_in[9];
    const float* cgamma = (const float*)d_in[10];
    const float* cbeta  = (const float*)d_in[11];
    const float* cWp    = (const float*)d_in[12];
    const float* cbp    = (const float*)d_in[13];
    const float* Ws     = (const float*)d_in[14];
    const float* bs     = (const float*)d_in[15];
    const float* fWe    = (const float*)d_in[16];
    const float* fbe    = (const float*)d_in[17];
    const float* fWl    = (const float*)d_in[18];
    const float* fbl    = (const float*)d_in[19];
    const float* fWgl   = (const float*)d_in[20];
    const float* fbgl   = (const float*)d_in[21];
    const float* fWgs   = (const float*)d_in[22];
    const float* fbgs   = (const float*)d_in[23];
    const float* fgamma = (const float*)d_in[24];
    const float* fbeta  = (const float*)d_in[25];
    float* out = (float*)d_out;

    cudaFuncSetAttribute(k_grn_mma, cudaFuncAttributeMaxDynamicSharedMemorySize, SMTOT);
    cudaFuncSetAttribute(k_biggemm_mma, cudaFuncAttributeMaxDynamicSharedMemorySize, BG_TOT);

    k_wprep2<<<8192, 256>>>(fWe, fWl, fWgl, fWgs);
    k_biggemm_mma<<<dim3(G_, 2, 2), 256, BG_TOT>>>(inputs, stat, cWe, cWp);
    k_select<<<128, 128>>>(cbe, cWl, cbl, cWgl, cbgl, cWgs, cbgs,
                           cgamma, cbeta, cbp, Ws, bs);
    k_grn_mma<<<dim3(B_, F_), 512, SMTOT>>>(inputs, fbe, fbl, fbgl, fbgs,
                                            fgamma, fbeta);
    k_combine<<<1024, 256>>>(out);
}

// round 14
// speedup vs baseline: 3.1832x; 1.0227x over previous
#include <cuda_runtime.h>
#include <cuda_bf16.h>
#include <math.h>
#include <stdint.h>

#define B_   128
#define S_   64
#define F_   32
#define D_   128
#define U_   128
#define DS_  128
#define SFD  262144          // S*F*D
#define NTILES 2049          // DIN / 128
#define G_   296             // split-K groups for big GEMM

// deterministic split-K scratch: [G_][2][128][128]
__device__ float g_partial[(size_t)G_ * 2 * 128 * 128];
__device__ float g_wsel[B_ * F_];
// per-feature GRN outputs (unweighted LN results): [F][B*S][U] = 134 MB
__device__ float g_part[(size_t)F_ * B_ * S_ * U_];
// fragment-linear bf16 hi/lo weight images: per f 256KB = 4 stages x (hi32K|lo32K)
__device__ unsigned char g_wimg[(size_t)F_ * 262144];

// ---------------------------------------------------------------------------
// mma.sync / ldmatrix / cp.async helpers (sm_80-compatible, OK on compute_103)
// ---------------------------------------------------------------------------
__device__ __forceinline__ uint32_t smem_u32(const void* p) {
    uint32_t a;
    asm("{ .reg .u64 t; cvta.to.shared.u64 t, %1; cvt.u32.u64 %0, t; }"
        : "=r"(a) : "l"(p));
    return a;
}
__device__ __forceinline__ void ldm4(uint32_t r[4], uint32_t addr) {
    asm volatile("ldmatrix.sync.aligned.m8n8.x4.shared.b16 {%0,%1,%2,%3}, [%4];"
        : "=r"(r[0]), "=r"(r[1]), "=r"(r[2]), "=r"(r[3]) : "r"(addr));
}
__device__ __forceinline__ void ldm4t(uint32_t r[4], uint32_t addr) {
    asm volatile("ldmatrix.sync.aligned.m8n8.x4.trans.shared.b16 {%0,%1,%2,%3}, [%4];"
        : "=r"(r[0]), "=r"(r[1]), "=r"(r[2]), "=r"(r[3]) : "r"(addr));
}
__device__ __forceinline__ uint32_t lds32(uint32_t a) {
    uint32_t v;
    asm volatile("ld.shared.b32 %0, [%1];" : "=r"(v) : "r"(a));
    return v;
}
__device__ __forceinline__ void mma_bf16(float c[4], const uint32_t a[4],
                                         uint32_t b0, uint32_t b1) {
    asm volatile(
        "mma.sync.aligned.m16n8k16.row.col.f32.bf16.bf16.f32 "
        "{%0,%1,%2,%3}, {%4,%5,%6,%7}, {%8,%9}, {%0,%1,%2,%3};"
        : "+f"(c[0]), "+f"(c[1]), "+f"(c[2]), "+f"(c[3])
        : "r"(a[0]), "r"(a[1]), "r"(a[2]), "r"(a[3]), "r"(b0), "r"(b1));
}
__device__ __forceinline__ void cpa16(uint32_t dst, const void* src) {
    asm volatile("cp.async.cg.shared.global [%0], [%1], 16;"
                 :: "r"(dst), "l"(src));
}
#define CP_COMMIT() asm volatile("cp.async.commit_group;")
#define CP_WAIT(n)  asm volatile("cp.async.wait_group %0;" :: "n"(n))

// split fp32 pair -> packed bf16 hi word + lo word
__device__ __forceinline__ void split2(float v0, float v1,
                                       uint32_t& hw, uint32_t& lw) {
    __nv_bfloat16 h0 = __float2bfloat16(v0);
    __nv_bfloat16 h1 = __float2bfloat16(v1);
    unsigned short l0 = __bfloat16_as_ushort(__float2bfloat16(v0 - __bfloat162float(h0)));
    unsigned short l1 = __bfloat16_as_ushort(__float2bfloat16(v1 - __bfloat162float(h1)));
    hw = (uint32_t)__bfloat16_as_ushort(h0) | ((uint32_t)__bfloat16_as_ushort(h1) << 16);
    lw = (uint32_t)l0 | ((uint32_t)l1 << 16);
}

// ---------------------------------------------------------------------------
// Kernel 1: big split-K GEMM on mma.sync bf16 (unchanged from R13)
// ---------------------------------------------------------------------------
#define BG_AH 0
#define BG_AL 34816
#define BG_WH 69632
#define BG_WL 88064
#define BG_TOT 106496

__global__ __launch_bounds__(256, 2) void k_biggemm_mma(
    const float* __restrict__ inputs, const float* __restrict__ stat,
    const float* __restrict__ cWe, const float* __restrict__ cWp)
{
    extern __shared__ __align__(16) unsigned char smem[];
    const uint32_t sb32 = smem_u32(smem);
    const int g = blockIdx.x, which = blockIdx.y, nhalf = blockIdx.z;
    const float* __restrict__ W = which ? cWp : cWe;
    const int nbase = nhalf * 64;

    const int t = threadIdx.x;
    const int warp = t >> 5, lane = t & 31;
    const int wm = warp >> 1, wn = warp & 1;
    const int m0 = wm * 32;

    float C[2][4][4];
#pragma unroll
    for (int mt = 0; mt < 2; mt++)
#pragma unroll
        for (int n8 = 0; n8 < 4; n8++)
#pragma unroll
            for (int e = 0; e < 4; e++) C[mt][n8][e] = 0.f;

    const uint32_t aH = sb32 + BG_AH, aL = sb32 + BG_AL;
    const uint32_t wH = sb32 + BG_WH, wL = sb32 + BG_WL;

    for (int tile = g; tile < NTILES; tile += G_) {
        const float* vb; long vstr;
        if (tile < 2048) { vb = inputs + (long)tile * 128; vstr = SFD; }
        else             { vb = stat;                      vstr = DS_; }
        const float* Wg = W + (long)tile * 16384 + nbase;

        __syncthreads();

#pragma unroll
        for (int i = 0; i < 16; i++) {
            int idx4 = t + i * 256;
            int row = idx4 >> 5;
            int c4 = (idx4 & 31) * 4;
            float4 v = *(const float4*)(vb + (long)row * vstr + c4);
            uint32_t hw0, lw0, hw1, lw1;
            split2(v.x, v.y, hw0, lw0);
            split2(v.z, v.w, hw1, lw1);
            uint32_t off = ((uint32_t)row * 136 + (uint32_t)c4) * 2;
            *(uint32_t*)(smem + BG_AH + off)     = hw0;
            *(uint32_t*)(smem + BG_AH + off + 4) = hw1;
            *(uint32_t*)(smem + BG_AL + off)     = lw0;
            *(uint32_t*)(smem + BG_AL + off + 4) = lw1;
        }
#pragma unroll
        for (int i = 0; i < 8; i++) {
            int idx4 = t + i * 256;
            int kr = idx4 >> 4;
            int c4 = (idx4 & 15) * 4;
            float4 v = *(const float4*)(Wg + (long)kr * 128 + c4);
            uint32_t hw0, lw0, hw1, lw1;
            split2(v.x, v.y, hw0, lw0);
            split2(v.z, v.w, hw1, lw1);
            uint32_t off = ((uint32_t)kr * 72 + (uint32_t)c4) * 2;
            *(uint32_t*)(smem + BG_WH + off)     = hw0;
            *(uint32_t*)(smem + BG_WH + off + 4) = hw1;
            *(uint32_t*)(smem + BG_WL + off)     = lw0;
            *(uint32_t*)(smem + BG_WL + off + 4) = lw1;
        }
        __syncthreads();

#pragma unroll
        for (int kt = 0; kt < 8; kt++) {
            uint32_t ah[2][4], al[2][4];
#pragma unroll
            for (int mt = 0; mt < 2; mt++) {
                uint32_t aoff = ((uint32_t)(m0 + mt * 16 + (lane & 15)) * 136
                                 + (uint32_t)kt * 16 + ((lane >> 4) << 3)) * 2;
                ldm4(ah[mt], aH + aoff);
                ldm4(al[mt], aL + aoff);
            }
            uint32_t bh[2][4], bl[2][4];
#pragma unroll
            for (int nt = 0; nt < 2; nt++) {
                uint32_t brow = (uint32_t)kt * 16 + ((lane >> 3) & 1) * 8 + (lane & 7);
                uint32_t bcol = (uint32_t)wn * 32 + nt * 16 + ((lane >> 4) << 3);
                uint32_t boff = (brow * 72 + bcol) * 2;
                ldm4t(bh[nt], wH + boff);
                ldm4t(bl[nt], wL + boff);
            }
#pragma unroll
            for (int mt = 0; mt < 2; mt++)
#pragma unroll
                for (int n8 = 0; n8 < 4; n8++) {
                    int nt = n8 >> 1, pr = (n8 & 1) * 2;
                    uint32_t b0h = bh[nt][pr], b1h = bh[nt][pr + 1];
                    uint32_t b0l = bl[nt][pr], b1l = bl[nt][pr + 1];
                    mma_bf16(C[mt][n8], ah[mt], b0h, b1h);
                    mma_bf16(C[mt][n8], al[mt], b0h, b1h);
                    mma_bf16(C[mt][n8], ah[mt], b0l, b1l);
                }
        }
    }

    float* dst = g_partial + ((long)g * 2 + which) * 16384 + nbase;
#pragma unroll
    for (int mt = 0; mt < 2; mt++)
#pragma unroll
        for (int n8 = 0; n8 < 4; n8++) {
            int row = m0 + mt * 16 + (lane >> 2);
            int col = wn * 32 + n8 * 8 + (lane & 3) * 2;
            float2 v0 = make_float2(C[mt][n8][0], C[mt][n8][1]);
            float2 v1 = make_float2(C[mt][n8][2], C[mt][n8][3]);
            *(float2*)(dst + (long)row * 128 + col)       = v0;
            *(float2*)(dst + (long)(row + 8) * 128 + col) = v1;
        }
}

// ---------------------------------------------------------------------------
// Weight prep for k_grn (unchanged)
// ---------------------------------------------------------------------------
__global__ __launch_bounds__(256) void k_wprep2(
    const float* __restrict__ fWe, const float* __restrict__ fWl,
    const float* __restrict__ fWgl, const float* __restrict__ fWgs)
{
    int idx = blockIdx.x * 256 + threadIdx.x;
    int f = idx >> 16;
    int w = idx & 65535;
    int seg = w >> 13;
    int widx = w & 8191;
    int stage = seg >> 1;
    int islo = seg & 1;
    int kt = widx >> 10;
    int r  = widx & 1023;
    int ntg = r >> 6;
    int q = r & 63;
    int reg = q >> 5;
    int lane = q & 31;
    int k0 = kt * 16 + (lane & 3) * 2 + reg * 8;
    int n  = ntg * 8 + (lane >> 2);
    const float* src = stage == 0 ? fWe : stage == 1 ? fWl
                     : stage == 2 ? fWgl : fWgs;
    float v0 = src[f * 16384 + k0 * 128 + n];
    float v1 = src[f * 16384 + (k0 + 1) * 128 + n];
    uint32_t word;
    if (!islo) {
        unsigned short h0 = __bfloat16_as_ushort(__float2bfloat16(v0));
        unsigned short h1 = __bfloat16_as_ushort(__float2bfloat16(v1));
        word = (uint32_t)h0 | ((uint32_t)h1 << 16);
    } else {
        __nv_bfloat16 h0 = __float2bfloat16(v0);
        __nv_bfloat16 h1 = __float2bfloat16(v1);
        unsigned short l0 = __bfloat16_as_ushort(__float2bfloat16(v0 - __bfloat162float(h0)));
        unsigned short l1 = __bfloat16_as_ushort(__float2bfloat16(v1 - __bfloat162float(h1)));
        word = (uint32_t)l0 | ((uint32_t)l1 << 16);
    }
    ((uint32_t*)(g_wimg + (size_t)f * 262144))[seg * 8192 + widx] = word;
}

// ---------------------------------------------------------------------------
// Kernel 2: selection head (unchanged)
// ---------------------------------------------------------------------------
__global__ __launch_bounds__(128) void k_select(
    const float* __restrict__ cbe,
    const float* __restrict__ cWl,  const float* __restrict__ cbl,
    const float* __restrict__ cWgl, const float* __restrict__ cbgl,
    const float* __restrict__ cWgs, const float* __restrict__ cbgs,
    const float* __restrict__ cgamma, const float* __restrict__ cbeta,
    const float* __restrict__ cbp,
    const float* __restrict__ Ws,   const float* __restrict__ bs)
{
    const int b = blockIdx.x, t = threadIdx.x;
    __shared__ float h[128], h2[128], yv[128];
    __shared__ float red[4];

    float s0 = 0.f, s1 = 0.f;
    const float* p = g_partial + b * 128 + t;
    for (int g = 0; g < G_; ++g) {
        s0 += p[(size_t)(g * 2 + 0) * 16384];
        s1 += p[(size_t)(g * 2 + 1) * 16384];
    }

    float hv = s0 + cbe[t];
    h[t] = hv > 0.f ? hv : expm1f(hv);
    __syncthreads();

    float a = 0.f;
    for (int k = 0; k < 128; k++) a += h[k] * cWl[k * 128 + t];
    h2[t] = a + cbl[t];
    __syncthreads();

    float gl = cbgl[t], gs = cbgs[t];
    for (int k = 0; k < 128; k++) {
        float hk = h2[k];
        gl += hk * cWgl[k * 128 + t];
        gs += hk * cWgs[k * 128 + t];
    }
    float r = s1 + cbp[t] + gl * (1.f / (1.f + expf(-gs)));

    float sm = r;
    for (int o = 16; o; o >>= 1) sm += __shfl_xor_sync(~0u, sm, o);
    if ((t & 31) == 0) red[t >> 5] = sm;
    __syncthreads();
    float mean = (red[0] + red[1] + red[2] + red[3]) * (1.f / 128.f);
    float d = r - mean;
    float sq = d * d;
    for (int o = 16; o; o >>= 1) sq += __shfl_xor_sync(~0u, sq, o);
    __syncthreads();
    if ((t & 31) == 0) red[t >> 5] = sq;
    __syncthreads();
    float var = (red[0] + red[1] + red[2] + red[3]) * (1.f / 128.f);
    yv[t] = d * rsqrtf(var + 1e-3f) * cgamma[t] + cbeta[t];
    __syncthreads();

    if (t < 32) {
        float l = bs[t];
        for (int k = 0; k < 128; k++) l += yv[k] * Ws[k * 32 + t];
        float mx = l;
        for (int o = 16; o; o >>= 1) mx = fmaxf(mx, __shfl_xor_sync(~0u, mx, o));
        float e = expf(l - mx);
        float ss = e;
        for (int o = 16; o; o >>= 1) ss += __shfl_xor_sync(~0u, ss, o);
        g_wsel[b * 32 + t] = e / ss;
    }
}

// ---------------------------------------------------------------------------
// Kernel 3: per-(batch-pair, feature) GRN on mma.sync bf16, M=128 per block.
// 512 thr = 16 warps (wm 4 x wn 4), each m32 x n32. gl spilled to dead W3
// slot (thread-private); residual x re-read from gmem at gating; zbuf in
// dead A area.
// ---------------------------------------------------------------------------
#define GM_SLOT0 0           // 64KB W1/W3, then gl spill
#define GM_SLOT1 65536       // 64KB W2/W4
#define GM_A_H   131072      // 34816: Ah [128][136] u16 ; zbuf after stage4
#define GM_A_L   165888      // 34816: Al
#define GM_B     200704      // 3072: biases
#define GM_TOT   203776

__device__ __forceinline__ void cp64k(uint32_t dst, const unsigned char* src, int t) {
#pragma unroll
    for (int i = 0; i < 8; i++) {
        int o = (t + i * 512) * 16;
        cpa16(dst + o, src + o);
    }
}

__device__ __forceinline__ void run_stage128(
    uint32_t aH, uint32_t aL, uint32_t wslot,
    int wm, int wn, int lane, float C[2][4][4])
{
#pragma unroll
    for (int mt = 0; mt < 2; mt++)
#pragma unroll
        for (int nt = 0; nt < 4; nt++)
#pragma unroll
            for (int e = 0; e < 4; e++) C[mt][nt][e] = 0.f;

#pragma unroll
    for (int kt = 0; kt < 8; kt++) {
        uint32_t ah[2][4], al[2][4];
#pragma unroll
        for (int mt = 0; mt < 2; mt++) {
            uint32_t aoff = ((uint32_t)(wm * 32 + mt * 16 + (lane & 15)) * 136
                             + (uint32_t)kt * 16 + ((lane >> 4) << 3)) * 2;
            ldm4(ah[mt], aH + aoff);
            ldm4(al[mt], aL + aoff);
        }
#pragma unroll
        for (int nt = 0; nt < 4; nt++) {
            uint32_t b = wslot + (uint32_t)((kt * 16 + wn * 4 + nt) * 64 + lane) * 4;
            uint32_t bh0 = lds32(b), bh1 = lds32(b + 128);
            uint32_t bl0 = lds32(b + 32768), bl1 = lds32(b + 32768 + 128);
#pragma unroll
            for (int mt = 0; mt < 2; mt++) {
                mma_bf16(C[mt][nt], ah[mt], bh0, bh1);
                mma_bf16(C[mt][nt], al[mt], bh0, bh1);
                mma_bf16(C[mt][nt], ah[mt], bl0, bl1);
            }
        }
    }
}

__device__ __forceinline__ void write_act128(
    float C[2][4][4], const float* sb, int boff, bool do_elu,
    unsigned char* smem, int wm, int wn, int lane)
{
#pragma unroll
    for (int mt = 0; mt < 2; mt++) {
        int r0 = wm * 32 + mt * 16 + (lane >> 2);
        int nc0 = wn * 32 + ((lane & 3) << 1);
#pragma unroll
        for (int nt = 0; nt < 4; nt++) {
            int n = nc0 + nt * 8;
            float b0 = sb[boff + n], b1 = sb[boff + n + 1];
#pragma unroll
            for (int half = 0; half < 2; half++) {
                int r = r0 + half * 8;
                float v0 = C[mt][nt][half * 2 + 0] + b0;
                float v1 = C[mt][nt][half * 2 + 1] + b1;
                if (do_elu) {
                    v0 = v0 > 0.f ? v0 : (__expf(v0) - 1.f);
                    v1 = v1 > 0.f ? v1 : (__expf(v1) - 1.f);
                }
                uint32_t hw, lw;
                split2(v0, v1, hw, lw);
                uint32_t off = ((uint32_t)r * 136 + (uint32_t)n) * 2;
                *(uint32_t*)(smem + GM_A_H + off) = hw;
                *(uint32_t*)(smem + GM_A_L + off) = lw;
            }
        }
    }
}

__global__ __launch_bounds__(512, 1) void k_grn_mma(
    const float* __restrict__ inputs,
    const float* __restrict__ fbe,  const float* __restrict__ fbl,
    const float* __restrict__ fbgl, const float* __restrict__ fbgs,
    const float* __restrict__ fgamma, const float* __restrict__ fbeta)
{
    extern __shared__ __align__(16) unsigned char smem[];
    const uint32_t sb32 = smem_u32(smem);
    float* sb   = (float*)(smem + GM_B);
    float* zbuf = (float*)(smem + GM_A_H);      // reused after stage4
    float* glsp = (float*)(smem + GM_SLOT0);    // gl spill after stage3

    const int t = threadIdx.x;
    const int warp = t >> 5, lane = t & 31;
    const int wm = warp >> 2, wn = warp & 3;
    const int p = blockIdx.x, f = blockIdx.y;   // batch-pair, feature
    const unsigned char* img = g_wimg + (size_t)f * 262144;

    cp64k(sb32 + GM_SLOT0, img,         t); CP_COMMIT();
    cp64k(sb32 + GM_SLOT1, img + 65536, t); CP_COMMIT();

    for (int i = t; i < 768; i += 512) {
        int a = i >> 7, j = i & 127;
        const float* src = a == 0 ? fbe : a == 1 ? fbl : a == 2 ? fbgl
                         : a == 3 ? fbgs : a == 4 ? fgamma : fbeta;
        sb[i] = src[f * 128 + j];
    }

    // prologue: x (128 rows) -> Ah/Al bf16 split. thread: row t>>2, cols (t&3)*32..+31
    {
        int row = t >> 2, c0 = (t & 3) * 32;
        const float* src = inputs + (size_t)(p * 128 + row) * 4096 + f * 128 + c0;
#pragma unroll
        for (int j = 0; j < 8; j++) {
            float4 v = *(const float4*)(src + j * 4);
            uint32_t hw0, lw0, hw1, lw1;
            split2(v.x, v.y, hw0, lw0);
            split2(v.z, v.w, hw1, lw1);
            uint32_t off = ((uint32_t)row * 136 + (uint32_t)(c0 + j * 4)) * 2;
            *(uint32_t*)(smem + GM_A_H + off)     = hw0;
            *(uint32_t*)(smem + GM_A_H + off + 4) = hw1;
            *(uint32_t*)(smem + GM_A_L + off)     = lw0;
            *(uint32_t*)(smem + GM_A_L + off + 4) = lw1;
        }
    }

    float C[2][4][4];
    const uint32_t aH = sb32 + GM_A_H, aL = sb32 + GM_A_L;
    const uint32_t slot0 = sb32 + GM_SLOT0, slot1 = sb32 + GM_SLOT1;

    CP_WAIT(1);                 // W1 arrived
    __syncthreads();

    // ---- stage 1: h = elu(x @ W1 + be) ----
    run_stage128(aH, aL, slot0, wm, wn, lane, C);
    __syncthreads();            // all reads of x + W1 done
    write_act128(C, sb, 0, true, smem, wm, wn, lane);
    cp64k(slot0, img + 131072, t); CP_COMMIT();   // W3 -> slot0
    CP_WAIT(1);                 // W2 arrived
    __syncthreads();

    // ---- stage 2: h2 = h @ W2 + bl ----
    run_stage128(aH, aL, slot1, wm, wn, lane, C);
    __syncthreads();
    write_act128(C, sb, 128, false, smem, wm, wn, lane);
    cp64k(slot1, img + 196608, t); CP_COMMIT();   // W4 -> slot1
    CP_WAIT(1);                 // W3 arrived
    __syncthreads();

    // ---- stage 3: gl = h2 @ W3 + bgl -> spill to slot0 (thread-private) ----
    run_stage128(aH, aL, slot0, wm, wn, lane, C);
    __syncthreads();            // all W3 reads done; slot0 now dead
    {
#pragma unroll
        for (int mt = 0; mt < 2; mt++) {
            int nc0 = wn * 32 + ((lane & 3) << 1);
#pragma unroll
            for (int nt = 0; nt < 4; nt++) {
                int n = nc0 + nt * 8;
                float b0 = sb[256 + n], b1 = sb[256 + n + 1];
                int e0 = mt * 16 + nt * 4;
                glsp[(e0 + 0) * 512 + t] = C[mt][nt][0] + b0;
                glsp[(e0 + 1) * 512 + t] = C[mt][nt][1] + b1;
                glsp[(e0 + 2) * 512 + t] = C[mt][nt][2] + b0;
                glsp[(e0 + 3) * 512 + t] = C[mt][nt][3] + b1;
            }
        }
    }
    CP_WAIT(0);                 // W4 arrived
    __syncthreads();

    // ---- stage 4: gs = h2 @ W4 + bgs ----
    run_stage128(aH, aL, slot1, wm, wn, lane, C);
    __syncthreads();            // all A (h2) reads done; A area -> zbuf

    // gating: z = x + gl * sigmoid(gs); x re-read from gmem in frag layout
    {
        const float* xbase = inputs + (size_t)(p * 128) * 4096 + f * 128;
#pragma unroll
        for (int mt = 0; mt < 2; mt++) {
            int r0 = wm * 32 + mt * 16 + (lane >> 2);
            int nc0 = wn * 32 + ((lane & 3) << 1);
#pragma unroll
            for (int nt = 0; nt < 4; nt++) {
                int n = nc0 + nt * 8;
                float bgs0 = sb[384 + n], bgs1 = sb[384 + n + 1];
                int e0 = mt * 16 + nt * 4;
#pragma unroll
                for (int half = 0; half < 2; half++) {
                    int r = r0 + half * 8;
                    float gl0 = glsp[(e0 + half * 2 + 0) * 512 + t];
                    float gl1 = glsp[(e0 + half * 2 + 1) * 512 + t];
                    float gs0 = C[mt][nt][half * 2 + 0] + bgs0;
                    float gs1 = C[mt][nt][half * 2 + 1] + bgs1;
                    float s0 = __fdividef(1.f, 1.f + __expf(-gs0));
                    float s1 = __fdividef(1.f, 1.f + __expf(-gs1));
                    float2 xv = *(const float2*)(xbase + (size_t)r * 4096 + n);
                    float2 z;
                    z.x = xv.x + gl0 * s0;
                    z.y = xv.y + gl1 * s1;
                    *(float2*)(zbuf + r * 132 + n) = z;
                }
            }
        }
    }
    __syncthreads();

    // LayerNorm per row (4 threads/row, 32 cols each), write to g_part
    {
        int row = t >> 2, sub = t & 3;
        const float* zr = zbuf + row * 132 + sub * 32;
        float4 z4[8];
        float sum = 0.f, sq = 0.f;
#pragma unroll
        for (int j = 0; j < 8; j++) {
            z4[j] = *(const float4*)(zr + j * 4);
            sum += z4[j].x + z4[j].y + z4[j].z + z4[j].w;
            sq  += z4[j].x * z4[j].x + z4[j].y * z4[j].y
                 + z4[j].z * z4[j].z + z4[j].w * z4[j].w;
        }
#pragma unroll
        for (int o = 1; o < 4; o <<= 1) {
            sum += __shfl_xor_sync(~0u, sum, o);
            sq  += __shfl_xor_sync(~0u, sq, o);
        }
        float mean = sum * (1.f / 128.f);
        float var  = sq * (1.f / 128.f) - mean * mean;
        float rstd = rsqrtf(var + 1e-3f);
        float* dst = g_part + (size_t)f * 1048576
                   + (size_t)(p * 128 + row) * 128 + sub * 32;
#pragma unroll
        for (int j = 0; j < 8; j++) {
            int c = sub * 32 + j * 4;
            float4 o;
            o.x = (z4[j].x - mean) * rstd * sb[512 + c + 0] + sb[640 + c + 0];
            o.y = (z4[j].y - mean) * rstd * sb[512 + c + 1] + sb[640 + c + 1];
            o.z = (z4[j].z - mean) * rstd * sb[512 + c + 2] + sb[640 + c + 2];
            o.w = (z4[j].w - mean) * rstd * sb[512 + c + 3] + sb[640 + c + 3];
            *(float4*)(dst + j * 4) = o;
        }
    }
}

// ---------------------------------------------------------------------------
// Kernel 4: deterministic softmax-weighted combine over features (unchanged).
// ---------------------------------------------------------------------------
__global__ __launch_bounds__(256) void k_combine(float* __restrict__ out)
{
    __shared__ float ws[32];
    const int b = blockIdx.x >> 3;
    if (threadIdx.x < 32) ws[threadIdx.x] = g_wsel[b * 32 + threadIdx.x];
    __syncthreads();

    const size_t gid = (size_t)blockIdx.x * 256 + threadIdx.x;
    float4 acc = make_float4(0.f, 0.f, 0.f, 0.f);
#pragma unroll 8
    for (int f = 0; f < 32; f++) {
        float4 v = ((const float4*)g_part)[(size_t)f * 262144 + gid];
        float w = ws[f];
        acc.x += w * v.x; acc.y += w * v.y;
        acc.z += w * v.z; acc.w += w * v.w;
    }
    ((float4*)out)[gid] = acc;
}

// ---------------------------------------------------------------------------
extern "C" void kernel_launch(void* const* d_in, const int* in_sizes, int n_in,
                              void* d_out, int out_size)
{
    const float* inputs = (const float*)d_in[0];
    const float* stat   = (const float*)d_in[1];
    const float* cWe    = (const float*)d_in[2];
    const float* cbe    = (const float*)d_in[3];
    const float* cWl    = (const float*)d_in[4];
    const float* cbl    = (const float*)d_in[5];
    const float* cWgl   = (const float*)d_in[6];
    const float* cbgl   = (const float*)d_in[7];
    const float* cWgs   = (const float*)d_in[8];
    const float* cbgs   = (const float*)d_in[9];
    const float* cgamma = (const float*)d_in[10];
    const float* cbeta  = (const float*)d_in[11];
    const float* cWp    = (const float*)d_in[12];
    const float* cbp    = (const float*)d_in[13];
    const float* Ws     = (const float*)d_in[14];
    const float* bs     = (const float*)d_in[15];
    const float* fWe    = (const float*)d_in[16];
    const float* fbe    = (const float*)d_in[17];
    const float* fWl    = (const float*)d_in[18];
    const float* fbl    = (const float*)d_in[19];
    const float* fWgl   = (const float*)d_in[20];
    const float* fbgl   = (const float*)d_in[21];
    const float* fWgs   = (const float*)d_in[22];
    const float* fbgs   = (const float*)d_in[23];
    const float* fgamma = (const float*)d_in[24];
    const float* fbeta  = (const float*)d_in[25];
    float* out = (float*)d_out;

    cudaFuncSetAttribute(k_grn_mma, cudaFuncAttributeMaxDynamicSharedMemorySize, GM_TOT);
    cudaFuncSetAttribute(k_biggemm_mma, cudaFuncAttributeMaxDynamicSharedMemorySize, BG_TOT);

    k_wprep2<<<8192, 256>>>(fWe, fWl, fWgl, fWgs);
    k_biggemm_mma<<<dim3(G_, 2, 2), 256, BG_TOT>>>(inputs, stat, cWe, cWp);
    k_select<<<128, 128>>>(cbe, cWl, cbl, cWgl, cbgl, cWgs, cbgs,
                           cgamma, cbeta, cbp, Ws, bs);
    k_grn_mma<<<dim3(64, F_), 512, GM_TOT>>>(inputs, fbe, fbl, fbgl, fbgs,
                                             fgamma, fbeta);
    k_combine<<<1024, 256>>>(out);
}